// round 1
// baseline (speedup 1.0000x reference)
#include <cuda_runtime.h>

// Problem constants
#define BB      64
#define IN_CH   64
#define OUT_CH  64
#define NG      2048
#define MODES   512
#define RROWS   (BB * IN_CH)   // 4096 rows for both stage-1 (b,i) and stage-3 (b,o)

// ---------------------------------------------------------------------------
// Scratch (static __device__ globals -- no allocation at runtime)
// ---------------------------------------------------------------------------
__device__ float g_Mf[NG * MODES];              // Mf[n*MODES + k] = cos(pi*k*n/2047) * c[n]   (forward DCT-I, first 512 modes)
__device__ float g_Bi[MODES * NG];              // Bi[k*NG + n]  = cos(pi*k*n/2047) * c[k]     (inverse DCT-I, first 512 coeffs)
__device__ float g_C1[MODES * RROWS];           // C1[k*4096 + (b*64+i)]
__device__ float g_C2[MODES * RROWS];           // C2[k*4096 + (b*64+o)]
__device__ float g_Wt[MODES * IN_CH * OUT_CH];  // Wt[k*4096 + i*64 + o]

// ---------------------------------------------------------------------------
// Kernel 0: build the two DCT-I operator matrices.
// cos(pi*k*n/(N-1)) computed via cospif after exact integer reduction mod 2(N-1)
// ---------------------------------------------------------------------------
__global__ void init_M_kernel() {
    int idx = blockIdx.x * blockDim.x + threadIdx.x;
    if (idx >= NG * MODES) return;
    int n = idx / MODES;
    int k = idx - n * MODES;
    int m = (n * k) % (2 * (NG - 1));              // exact; n*k < 2^21
    float v = cospif((float)m * (1.0f / (float)(NG - 1)));
    float cn = (n == 0 || n == NG - 1) ? 1.0f : 2.0f;
    float ck = (k == 0) ? 1.0f : 2.0f;
    g_Mf[n * MODES + k] = v * cn;
    g_Bi[k * NG + n]    = v * ck;
}

// ---------------------------------------------------------------------------
// Kernel 1: transpose weights [i,o,k] -> Wt[k][i*64+o]   (rows=4096, cols=512)
// ---------------------------------------------------------------------------
__global__ void transpose_W_kernel(const float* __restrict__ w) {
    __shared__ float tile[32][33];
    int kBase = blockIdx.x * 32;   // mode dim
    int rBase = blockIdx.y * 32;   // (i*64+o) dim
    int tx = threadIdx.x, ty = threadIdx.y;   // (32, 8)
#pragma unroll
    for (int j = 0; j < 32; j += 8)
        tile[ty + j][tx] = w[(rBase + ty + j) * MODES + kBase + tx];
    __syncthreads();
#pragma unroll
    for (int j = 0; j < 32; j += 8)
        g_Wt[(kBase + ty + j) * RROWS + rBase + tx] = tile[tx][ty + j];
}

// ---------------------------------------------------------------------------
// Kernel 2: GEMM1 -- C1[k][r] = sum_n X[r][n] * Mf[n][k]
//   M=4096(r), N=512(k modes), K=2048(grid). Output stored TRANSPOSED (k-major).
//   128x128 block tile, BK=16, 8x8 per thread (split-4 in n).
// ---------------------------------------------------------------------------
__global__ __launch_bounds__(256) void gemm1_kernel(const float* __restrict__ X) {
    const int BM = 128, BN = 128, BK = 16;
    __shared__ float As[BK][BM + 1];   // [kk][m], +1 pad kills transpose-write conflicts
    __shared__ float Bs[BK][BN];       // [kk][n], float4-friendly

    int bm = blockIdx.y * BM;          // r base
    int bn = blockIdx.x * BN;          // mode base
    int tid = (int)threadIdx.x;
    int tx = tid & 15, ty = tid >> 4;

    float acc[8][8];
#pragma unroll
    for (int i = 0; i < 8; i++)
#pragma unroll
        for (int j = 0; j < 8; j++) acc[i][j] = 0.0f;

    for (int k0 = 0; k0 < NG; k0 += BK) {
        // A tile: X[bm+row][k0+cg..cg+3], transpose into As[kk][m]
#pragma unroll
        for (int l = 0; l < 2; l++) {
            int f = tid + l * 256;                 // 512 float4 total
            int row = f >> 2;
            int cg = (f & 3) << 2;
            float4 v = *(const float4*)&X[(bm + row) * NG + k0 + cg];
            As[cg + 0][row] = v.x;
            As[cg + 1][row] = v.y;
            As[cg + 2][row] = v.z;
            As[cg + 3][row] = v.w;
        }
        // B tile: Mf[(k0+kk)][bn + ...] -- row contiguous
#pragma unroll
        for (int l = 0; l < 2; l++) {
            int f = tid + l * 256;
            int kk = f >> 5;
            int cg = (f & 31) << 2;
            *(float4*)&Bs[kk][cg] = *(const float4*)&g_Mf[(k0 + kk) * MODES + bn + cg];
        }
        __syncthreads();

#pragma unroll
        for (int kk = 0; kk < BK; kk++) {
            float a[8], b[8];
#pragma unroll
            for (int i = 0; i < 8; i++) a[i] = As[kk][ty * 8 + i];
            float4 b0 = *(const float4*)&Bs[kk][tx * 4];
            float4 b1 = *(const float4*)&Bs[kk][64 + tx * 4];
            b[0] = b0.x; b[1] = b0.y; b[2] = b0.z; b[3] = b0.w;
            b[4] = b1.x; b[5] = b1.y; b[6] = b1.z; b[7] = b1.w;
#pragma unroll
            for (int i = 0; i < 8; i++)
#pragma unroll
                for (int j = 0; j < 8; j++) acc[i][j] += a[i] * b[j];
        }
        __syncthreads();
    }

    // Write C1[kc][bm + ty*8 + i]; thread's modes: bn + {tx*4+j, 64+tx*4+j}
#pragma unroll
    for (int jj = 0; jj < 2; jj++) {
#pragma unroll
        for (int j = 0; j < 4; j++) {
            int kc = bn + jj * 64 + tx * 4 + j;
            int jc = jj * 4 + j;
            float4 v0 = make_float4(acc[0][jc], acc[1][jc], acc[2][jc], acc[3][jc]);
            float4 v1 = make_float4(acc[4][jc], acc[5][jc], acc[6][jc], acc[7][jc]);
            *(float4*)&g_C1[kc * RROWS + bm + ty * 8]     = v0;
            *(float4*)&g_C1[kc * RROWS + bm + ty * 8 + 4] = v1;
        }
    }
}

// ---------------------------------------------------------------------------
// Kernel 3: per-mode channel mixing.
//   For each mode k: C2[k][b*64+o] = sum_i C1[k][b*64+i] * Wt[k][i*64+o]
//   One block per mode; 64x64x64 GEMM entirely in smem, 4x4 per thread.
// ---------------------------------------------------------------------------
__global__ __launch_bounds__(256) void mix_kernel() {
    int k = blockIdx.x;
    __shared__ float As[64][65];   // [b][i]
    __shared__ float Ws[64][65];   // [i][o]
    const float* a = &g_C1[k * RROWS];
    const float* w = &g_Wt[k * RROWS];
    int tid = (int)threadIdx.x;
#pragma unroll
    for (int l = 0; l < 16; l++) {
        int idx = tid + l * 256;
        int r = idx >> 6, c = idx & 63;
        As[r][c] = a[idx];
        Ws[r][c] = w[idx];
    }
    __syncthreads();

    int tx = tid & 15, ty = tid >> 4;
    float acc[4][4];
#pragma unroll
    for (int p = 0; p < 4; p++)
#pragma unroll
        for (int q = 0; q < 4; q++) acc[p][q] = 0.0f;

#pragma unroll 8
    for (int i = 0; i < 64; i++) {
        float av[4], wv[4];
#pragma unroll
        for (int p = 0; p < 4; p++) av[p] = As[ty * 4 + p][i];
#pragma unroll
        for (int q = 0; q < 4; q++) wv[q] = Ws[i][tx * 4 + q];
#pragma unroll
        for (int p = 0; p < 4; p++)
#pragma unroll
            for (int q = 0; q < 4; q++) acc[p][q] += av[p] * wv[q];
    }

    float* c2 = &g_C2[k * RROWS];
#pragma unroll
    for (int p = 0; p < 4; p++) {
        float4 v = make_float4(acc[p][0], acc[p][1], acc[p][2], acc[p][3]);
        *(float4*)&c2[(ty * 4 + p) * 64 + tx * 4] = v;
    }
}

// ---------------------------------------------------------------------------
// Kernel 4: GEMM3 -- out[r][n] = sum_k C2[k][r] * Bi[k][n]
//   M=4096(r), N=2048(grid), K=512(modes). A is K-major (no smem transpose).
// ---------------------------------------------------------------------------
__global__ __launch_bounds__(256) void gemm3_kernel(float* __restrict__ out) {
    const int BM = 128, BN = 128, BK = 16;
    __shared__ float As[BK][BM + 4];   // pad=4 keeps rows 16B-aligned for float4 writes
    __shared__ float Bs[BK][BN];

    int bm = blockIdx.y * BM;          // r base
    int bn = blockIdx.x * BN;          // grid-point base
    int tid = (int)threadIdx.x;
    int tx = tid & 15, ty = tid >> 4;

    float acc[8][8];
#pragma unroll
    for (int i = 0; i < 8; i++)
#pragma unroll
        for (int j = 0; j < 8; j++) acc[i][j] = 0.0f;

    for (int k0 = 0; k0 < MODES; k0 += BK) {
        // A tile: C2[(k0+kk)][bm + mg..] -- already K-major, contiguous in m
#pragma unroll
        for (int l = 0; l < 2; l++) {
            int f = tid + l * 256;
            int kk = f >> 5;
            int mg = (f & 31) << 2;
            *(float4*)&As[kk][mg] = *(const float4*)&g_C2[(k0 + kk) * RROWS + bm + mg];
        }
        // B tile: Bi[(k0+kk)][bn + ...]
#pragma unroll
        for (int l = 0; l < 2; l++) {
            int f = tid + l * 256;
            int kk = f >> 5;
            int cg = (f & 31) << 2;
            *(float4*)&Bs[kk][cg] = *(const float4*)&g_Bi[(k0 + kk) * NG + bn + cg];
        }
        __syncthreads();

#pragma unroll
        for (int kk = 0; kk < BK; kk++) {
            float a[8], b[8];
#pragma unroll
            for (int i = 0; i < 8; i++) a[i] = As[kk][ty * 8 + i];
            float4 b0 = *(const float4*)&Bs[kk][tx * 4];
            float4 b1 = *(const float4*)&Bs[kk][64 + tx * 4];
            b[0] = b0.x; b[1] = b0.y; b[2] = b0.z; b[3] = b0.w;
            b[4] = b1.x; b[5] = b1.y; b[6] = b1.z; b[7] = b1.w;
#pragma unroll
            for (int i = 0; i < 8; i++)
#pragma unroll
                for (int j = 0; j < 8; j++) acc[i][j] += a[i] * b[j];
        }
        __syncthreads();
    }

    // Write out[r][n]: per thread 8 rows, cols bn + {tx*4.., 64+tx*4..}
#pragma unroll
    for (int i = 0; i < 8; i++) {
        int r = bm + ty * 8 + i;
        float4 v0 = make_float4(acc[i][0], acc[i][1], acc[i][2], acc[i][3]);
        float4 v1 = make_float4(acc[i][4], acc[i][5], acc[i][6], acc[i][7]);
        *(float4*)&out[r * NG + bn + tx * 4]      = v0;
        *(float4*)&out[r * NG + bn + 64 + tx * 4] = v1;
    }
}

// ---------------------------------------------------------------------------
// Launch
// ---------------------------------------------------------------------------
extern "C" void kernel_launch(void* const* d_in, const int* in_sizes, int n_in,
                              void* d_out, int out_size) {
    const float* x = (const float*)d_in[0];   // [64, 64, 2048] f32
    const float* w = (const float*)d_in[1];   // [64, 64, 512]  f32
    float* out = (float*)d_out;               // [64, 64, 2048] f32

    init_M_kernel<<<(NG * MODES + 255) / 256, 256>>>();
    transpose_W_kernel<<<dim3(MODES / 32, RROWS / 32), dim3(32, 8)>>>(w);
    gemm1_kernel<<<dim3(MODES / 128, RROWS / 128), 256>>>(x);
    mix_kernel<<<MODES, 256>>>();
    gemm3_kernel<<<dim3(NG / 128, RROWS / 128), 256>>>(out);
}

// round 2
// speedup vs baseline: 1.7954x; 1.7954x over previous
#include <cuda_runtime.h>
#include <cuda_bf16.h>
#include <stdint.h>

#define BB      64
#define NG      2048
#define MODES   512
#define RROWS   4096

// ---------------------------------------------------------------------------
// Static device scratch
// ---------------------------------------------------------------------------
__device__ __align__(16) __nv_bfloat16 g_B1T_hi[MODES * NG];   // [mode][n]  forward op, c[n] folded
__device__ __align__(16) __nv_bfloat16 g_B1T_lo[MODES * NG];
__device__ __align__(16) __nv_bfloat16 g_B3T_hi[NG * MODES];   // [n][mode]  inverse op, c[k] folded
__device__ __align__(16) __nv_bfloat16 g_B3T_lo[NG * MODES];
__device__ __align__(16) __nv_bfloat16 g_Xhi[RROWS * NG];      // [r][n]
__device__ __align__(16) __nv_bfloat16 g_Xlo[RROWS * NG];
__device__ __align__(16) __nv_bfloat16 g_C2t_hi[RROWS * MODES];// [r][k]
__device__ __align__(16) __nv_bfloat16 g_C2t_lo[RROWS * MODES];
__device__ float g_C1[MODES * RROWS];                          // [k][r] fp32
__device__ float g_C2[MODES * RROWS];                          // [k][r] fp32
__device__ float g_Wt[MODES * RROWS];                          // [k][i*64+o] fp32

// ---------------------------------------------------------------------------
// bf16 hi/lo split helper
// ---------------------------------------------------------------------------
__device__ __forceinline__ void split_bf16(float v, __nv_bfloat16& hi, __nv_bfloat16& lo) {
    hi = __float2bfloat16(v);
    lo = __float2bfloat16(v - __bfloat162float(hi));
}

// ---------------------------------------------------------------------------
// Kernel 0: build both DCT-I operator matrices, transposed + hi/lo split.
// ---------------------------------------------------------------------------
__global__ void init_M_kernel() {
    int idx = blockIdx.x * blockDim.x + threadIdx.x;
    if (idx >= MODES * NG) return;
    // B1T[k][n] = cos(pi*k*n/2047) * c[n]   (coalesced along n)
    {
        int k = idx / NG, n = idx - (idx / NG) * NG;
        int m = (n * k) % (2 * (NG - 1));
        float v = cospif((float)m * (1.0f / (float)(NG - 1)));
        float cn = (n == 0 || n == NG - 1) ? 1.0f : 2.0f;
        split_bf16(v * cn, g_B1T_hi[idx], g_B1T_lo[idx]);
    }
    // B3T[n][k] = cos(pi*k*n/2047) * c[k]   (coalesced along k)
    {
        int n = idx / MODES, k = idx - (idx / MODES) * MODES;
        int m = (n * k) % (2 * (NG - 1));
        float v = cospif((float)m * (1.0f / (float)(NG - 1)));
        float ck = (k == 0) ? 1.0f : 2.0f;
        split_bf16(v * ck, g_B3T_hi[idx], g_B3T_lo[idx]);
    }
}

// ---------------------------------------------------------------------------
// Kernel 1: split X into bf16 hi/lo
// ---------------------------------------------------------------------------
__global__ void split_X_kernel(const float* __restrict__ x) {
    int idx = blockIdx.x * blockDim.x + threadIdx.x;   // one float4 per thread
    if (idx >= RROWS * NG / 4) return;
    float4 v = ((const float4*)x)[idx];
    float f[4] = {v.x, v.y, v.z, v.w};
    __nv_bfloat16 h[4], l[4];
#pragma unroll
    for (int i = 0; i < 4; i++) split_bf16(f[i], h[i], l[i]);
    union { __nv_bfloat16 b[4]; uint2 u; } ph, pl;
#pragma unroll
    for (int i = 0; i < 4; i++) { ph.b[i] = h[i]; pl.b[i] = l[i]; }
    *(uint2*)&g_Xhi[idx * 4] = ph.u;
    *(uint2*)&g_Xlo[idx * 4] = pl.u;
}

// ---------------------------------------------------------------------------
// Kernel 2: transpose weights [i,o,k] -> Wt[k][i*64+o]
// ---------------------------------------------------------------------------
__global__ void transpose_W_kernel(const float* __restrict__ w) {
    __shared__ float tile[32][33];
    int kBase = blockIdx.x * 32;
    int rBase = blockIdx.y * 32;
    int tx = threadIdx.x, ty = threadIdx.y;   // (32, 8)
#pragma unroll
    for (int j = 0; j < 32; j += 8)
        tile[ty + j][tx] = w[(rBase + ty + j) * MODES + kBase + tx];
    __syncthreads();
#pragma unroll
    for (int j = 0; j < 32; j += 8)
        g_Wt[(kBase + ty + j) * RROWS + rBase + tx] = tile[tx][ty + j];
}

// ---------------------------------------------------------------------------
// MMA helper: m16n8k16 row.col f32.bf16.bf16.f32
// ---------------------------------------------------------------------------
#define MMA_BF16(c, a, b)                                                       \
    asm volatile(                                                               \
        "mma.sync.aligned.m16n8k16.row.col.f32.bf16.bf16.f32 "                  \
        "{%0,%1,%2,%3},{%4,%5,%6,%7},{%8,%9},{%0,%1,%2,%3};\n"                  \
        : "+f"((c)[0]), "+f"((c)[1]), "+f"((c)[2]), "+f"((c)[3])                \
        : "r"((a)[0]), "r"((a)[1]), "r"((a)[2]), "r"((a)[3]),                   \
          "r"((b)[0]), "r"((b)[1]))

#define SLD 40   // padded smem row stride (bf16 elements) -> conflict-free frag loads

// ---------------------------------------------------------------------------
// GEMM1: C1[k][r] = sum_n X[r][n] * B1[n][k]
//   M=4096(r), N=512(mode), K=2048(n). CTA 128x128, BK=32.
//   8 warps (2 M x 4 N), warp tile 64x32, acc 4x4 m16n8 tiles.
//   Epilogue: smem-staged transpose to write C1[k][r] coalesced.
// ---------------------------------------------------------------------------
__global__ __launch_bounds__(256) void gemm1_mma() {
    __shared__ __align__(16) unsigned char s_raw[4 * 128 * SLD * 2];  // 40960 B
    __nv_bfloat16* sAhi = (__nv_bfloat16*)s_raw;
    __nv_bfloat16* sAlo = sAhi + 128 * SLD;
    __nv_bfloat16* sBhi = sAlo + 128 * SLD;
    __nv_bfloat16* sBlo = sBhi + 128 * SLD;

    int tid = (int)threadIdx.x;
    int bm = blockIdx.y * 128;   // r
    int bn = blockIdx.x * 128;   // mode
    int warp = tid >> 5, lane = tid & 31;
    int wm = warp >> 2, wn = warp & 3;
    int g = lane >> 2, t2 = (lane & 3) * 2;

    float acc[4][4][4];
#pragma unroll
    for (int a = 0; a < 4; a++)
#pragma unroll
        for (int b = 0; b < 4; b++)
#pragma unroll
            for (int c = 0; c < 4; c++) acc[a][b][c] = 0.0f;

    for (int k0 = 0; k0 < NG; k0 += 32) {
#pragma unroll
        for (int l = 0; l < 2; l++) {
            int idx = tid + l * 256;
            int row = idx >> 2, seg = (idx & 3) * 8;
            *(uint4*)&sAhi[row * SLD + seg] = *(const uint4*)&g_Xhi[(bm + row) * NG + k0 + seg];
            *(uint4*)&sAlo[row * SLD + seg] = *(const uint4*)&g_Xlo[(bm + row) * NG + k0 + seg];
            *(uint4*)&sBhi[row * SLD + seg] = *(const uint4*)&g_B1T_hi[(bn + row) * NG + k0 + seg];
            *(uint4*)&sBlo[row * SLD + seg] = *(const uint4*)&g_B1T_lo[(bn + row) * NG + k0 + seg];
        }
        __syncthreads();

#pragma unroll
        for (int ks = 0; ks < 2; ks++) {
            int ko = ks * 16 + t2;
            uint32_t ahi[4][4], alo[4][4], bhi[4][2], blo[4][2];
#pragma unroll
            for (int mi = 0; mi < 4; mi++) {
                int r0 = (wm * 64 + mi * 16 + g) * SLD;
                ahi[mi][0] = *(uint32_t*)&sAhi[r0 + ko];
                ahi[mi][1] = *(uint32_t*)&sAhi[r0 + 8 * SLD + ko];
                ahi[mi][2] = *(uint32_t*)&sAhi[r0 + ko + 8];
                ahi[mi][3] = *(uint32_t*)&sAhi[r0 + 8 * SLD + ko + 8];
                alo[mi][0] = *(uint32_t*)&sAlo[r0 + ko];
                alo[mi][1] = *(uint32_t*)&sAlo[r0 + 8 * SLD + ko];
                alo[mi][2] = *(uint32_t*)&sAlo[r0 + ko + 8];
                alo[mi][3] = *(uint32_t*)&sAlo[r0 + 8 * SLD + ko + 8];
            }
#pragma unroll
            for (int ni = 0; ni < 4; ni++) {
                int n0 = (wn * 32 + ni * 8 + g) * SLD;
                bhi[ni][0] = *(uint32_t*)&sBhi[n0 + ko];
                bhi[ni][1] = *(uint32_t*)&sBhi[n0 + ko + 8];
                blo[ni][0] = *(uint32_t*)&sBlo[n0 + ko];
                blo[ni][1] = *(uint32_t*)&sBlo[n0 + ko + 8];
            }
#pragma unroll
            for (int mi = 0; mi < 4; mi++)
#pragma unroll
                for (int ni = 0; ni < 4; ni++) {
                    MMA_BF16(acc[mi][ni], ahi[mi], bhi[ni]);
                    MMA_BF16(acc[mi][ni], ahi[mi], blo[ni]);
                    MMA_BF16(acc[mi][ni], alo[mi], bhi[ni]);
                }
        }
        __syncthreads();
    }

    // Epilogue: stage per r-half (64 rows), write C1[k][r] coalesced.
    float* cbuf = (float*)s_raw;   // 64 x 129 fp32 = 33 KB (fits in 40960)
#pragma unroll
    for (int half = 0; half < 2; half++) {
        if (wm == half) {
#pragma unroll
            for (int mi = 0; mi < 4; mi++)
#pragma unroll
                for (int ni = 0; ni < 4; ni++) {
                    int rl = mi * 16 + g;
                    int cl = wn * 32 + ni * 8 + t2;
                    cbuf[rl * 129 + cl]       = acc[mi][ni][0];
                    cbuf[rl * 129 + cl + 1]   = acc[mi][ni][1];
                    cbuf[(rl + 8) * 129 + cl]     = acc[mi][ni][2];
                    cbuf[(rl + 8) * 129 + cl + 1] = acc[mi][ni][3];
                }
        }
        __syncthreads();
#pragma unroll
        for (int p = 0; p < 32; p++) {
            int idx = tid + p * 256;           // 8192 = 128k x 64r
            int kc = idx >> 6;
            int r = idx & 63;
            g_C1[(bn + kc) * RROWS + bm + half * 64 + r] = cbuf[r * 129 + kc];
        }
        __syncthreads();
    }
}

// ---------------------------------------------------------------------------
// Kernel: per-mode channel mixing (fp32 SIMT; only 0.13 GMAC).
//   C2[k][b*64+o] = sum_i C1[k][b*64+i] * Wt[k][i*64+o]
// ---------------------------------------------------------------------------
__global__ __launch_bounds__(256) void mix_kernel() {
    int k = blockIdx.x;
    __shared__ float As[64][65];
    __shared__ float Ws[64][65];
    const float* a = &g_C1[k * RROWS];
    const float* w = &g_Wt[k * RROWS];
    int tid = (int)threadIdx.x;
#pragma unroll
    for (int l = 0; l < 16; l++) {
        int idx = tid + l * 256;
        int r = idx >> 6, c = idx & 63;
        As[r][c] = a[idx];
        Ws[r][c] = w[idx];
    }
    __syncthreads();

    int tx = tid & 15, ty = tid >> 4;
    float acc[4][4];
#pragma unroll
    for (int p = 0; p < 4; p++)
#pragma unroll
        for (int q = 0; q < 4; q++) acc[p][q] = 0.0f;

#pragma unroll 8
    for (int i = 0; i < 64; i++) {
        float av[4], wv[4];
#pragma unroll
        for (int p = 0; p < 4; p++) av[p] = As[ty * 4 + p][i];
#pragma unroll
        for (int q = 0; q < 4; q++) wv[q] = Ws[i][tx * 4 + q];
#pragma unroll
        for (int p = 0; p < 4; p++)
#pragma unroll
            for (int q = 0; q < 4; q++) acc[p][q] += av[p] * wv[q];
    }

    float* c2 = &g_C2[k * RROWS];
#pragma unroll
    for (int p = 0; p < 4; p++) {
        float4 v = make_float4(acc[p][0], acc[p][1], acc[p][2], acc[p][3]);
        *(float4*)&c2[(ty * 4 + p) * 64 + tx * 4] = v;
    }
}

// ---------------------------------------------------------------------------
// Kernel: transpose + split C2 [k][r] fp32 -> C2t hi/lo [r][k] bf16
// ---------------------------------------------------------------------------
__global__ void transpose_split_C2() {
    __shared__ float tile[32][33];
    int k0 = blockIdx.x * 32;
    int r0 = blockIdx.y * 32;
    int tx = threadIdx.x, ty = threadIdx.y;   // (32, 8)
#pragma unroll
    for (int j = 0; j < 32; j += 8)
        tile[ty + j][tx] = g_C2[(k0 + ty + j) * RROWS + r0 + tx];
    __syncthreads();
#pragma unroll
    for (int j = 0; j < 32; j += 8) {
        float v = tile[tx][ty + j];
        __nv_bfloat16 hi, lo;
        split_bf16(v, hi, lo);
        g_C2t_hi[(r0 + ty + j) * MODES + k0 + tx] = hi;
        g_C2t_lo[(r0 + ty + j) * MODES + k0 + tx] = lo;
    }
}

// ---------------------------------------------------------------------------
// GEMM3: out[r][n] = sum_k C2t[r][k] * B3[k][n]
//   M=4096(r), N=2048(n), K=512(mode). Same structure as GEMM1, direct store.
// ---------------------------------------------------------------------------
__global__ __launch_bounds__(256) void gemm3_mma(float* __restrict__ out) {
    __shared__ __align__(16) unsigned char s_raw[4 * 128 * SLD * 2];
    __nv_bfloat16* sAhi = (__nv_bfloat16*)s_raw;
    __nv_bfloat16* sAlo = sAhi + 128 * SLD;
    __nv_bfloat16* sBhi = sAlo + 128 * SLD;
    __nv_bfloat16* sBlo = sBhi + 128 * SLD;

    int tid = (int)threadIdx.x;
    int bm = blockIdx.y * 128;   // r
    int bn = blockIdx.x * 128;   // grid n
    int warp = tid >> 5, lane = tid & 31;
    int wm = warp >> 2, wn = warp & 3;
    int g = lane >> 2, t2 = (lane & 3) * 2;

    float acc[4][4][4];
#pragma unroll
    for (int a = 0; a < 4; a++)
#pragma unroll
        for (int b = 0; b < 4; b++)
#pragma unroll
            for (int c = 0; c < 4; c++) acc[a][b][c] = 0.0f;

    for (int k0 = 0; k0 < MODES; k0 += 32) {
#pragma unroll
        for (int l = 0; l < 2; l++) {
            int idx = tid + l * 256;
            int row = idx >> 2, seg = (idx & 3) * 8;
            *(uint4*)&sAhi[row * SLD + seg] = *(const uint4*)&g_C2t_hi[(bm + row) * MODES + k0 + seg];
            *(uint4*)&sAlo[row * SLD + seg] = *(const uint4*)&g_C2t_lo[(bm + row) * MODES + k0 + seg];
            *(uint4*)&sBhi[row * SLD + seg] = *(const uint4*)&g_B3T_hi[(bn + row) * MODES + k0 + seg];
            *(uint4*)&sBlo[row * SLD + seg] = *(const uint4*)&g_B3T_lo[(bn + row) * MODES + k0 + seg];
        }
        __syncthreads();

#pragma unroll
        for (int ks = 0; ks < 2; ks++) {
            int ko = ks * 16 + t2;
            uint32_t ahi[4][4], alo[4][4], bhi[4][2], blo[4][2];
#pragma unroll
            for (int mi = 0; mi < 4; mi++) {
                int r0 = (wm * 64 + mi * 16 + g) * SLD;
                ahi[mi][0] = *(uint32_t*)&sAhi[r0 + ko];
                ahi[mi][1] = *(uint32_t*)&sAhi[r0 + 8 * SLD + ko];
                ahi[mi][2] = *(uint32_t*)&sAhi[r0 + ko + 8];
                ahi[mi][3] = *(uint32_t*)&sAhi[r0 + 8 * SLD + ko + 8];
                alo[mi][0] = *(uint32_t*)&sAlo[r0 + ko];
                alo[mi][1] = *(uint32_t*)&sAlo[r0 + 8 * SLD + ko];
                alo[mi][2] = *(uint32_t*)&sAlo[r0 + ko + 8];
                alo[mi][3] = *(uint32_t*)&sAlo[r0 + 8 * SLD + ko + 8];
            }
#pragma unroll
            for (int ni = 0; ni < 4; ni++) {
                int n0 = (wn * 32 + ni * 8 + g) * SLD;
                bhi[ni][0] = *(uint32_t*)&sBhi[n0 + ko];
                bhi[ni][1] = *(uint32_t*)&sBhi[n0 + ko + 8];
                blo[ni][0] = *(uint32_t*)&sBlo[n0 + ko];
                blo[ni][1] = *(uint32_t*)&sBlo[n0 + ko + 8];
            }
#pragma unroll
            for (int mi = 0; mi < 4; mi++)
#pragma unroll
                for (int ni = 0; ni < 4; ni++) {
                    MMA_BF16(acc[mi][ni], ahi[mi], bhi[ni]);
                    MMA_BF16(acc[mi][ni], ahi[mi], blo[ni]);
                    MMA_BF16(acc[mi][ni], alo[mi], bhi[ni]);
                }
        }
        __syncthreads();
    }

    // Direct store: thread's c pairs are contiguous in n -> float2 stores.
#pragma unroll
    for (int mi = 0; mi < 4; mi++)
#pragma unroll
        for (int ni = 0; ni < 4; ni++) {
            int row = bm + wm * 64 + mi * 16 + g;
            int col = bn + wn * 32 + ni * 8 + t2;
            float2 v0 = make_float2(acc[mi][ni][0], acc[mi][ni][1]);
            float2 v1 = make_float2(acc[mi][ni][2], acc[mi][ni][3]);
            *(float2*)&out[row * NG + col] = v0;
            *(float2*)&out[(row + 8) * NG + col] = v1;
        }
}

// ---------------------------------------------------------------------------
// Launch
// ---------------------------------------------------------------------------
extern "C" void kernel_launch(void* const* d_in, const int* in_sizes, int n_in,
                              void* d_out, int out_size) {
    const float* x = (const float*)d_in[0];   // [64, 64, 2048] f32
    const float* w = (const float*)d_in[1];   // [64, 64, 512]  f32
    float* out = (float*)d_out;               // [64, 64, 2048] f32

    init_M_kernel<<<(MODES * NG + 255) / 256, 256>>>();
    split_X_kernel<<<(RROWS * NG / 4 + 255) / 256, 256>>>(x);
    transpose_W_kernel<<<dim3(MODES / 32, RROWS / 32), dim3(32, 8)>>>(w);
    gemm1_mma<<<dim3(MODES / 128, RROWS / 128), 256>>>();
    mix_kernel<<<MODES, 256>>>();
    transpose_split_C2<<<dim3(MODES / 32, RROWS / 32), dim3(32, 8)>>>();
    gemm3_mma<<<dim3(NG / 128, RROWS / 128), 256>>>(out);
}

// round 3
// speedup vs baseline: 3.7659x; 2.0975x over previous
#include <cuda_runtime.h>
#include <cuda_fp16.h>
#include <stdint.h>

#define BB      64
#define NG      2048
#define MODES   512
#define RROWS   4096
#define SLD     40   // padded smem row stride (half elements); 80B rows, 16B-aligned

// ---------------------------------------------------------------------------
// Static device scratch
// ---------------------------------------------------------------------------
__device__ __align__(16) __half g_B1T[MODES * NG];    // [mode][n]  forward op, c[n] folded
__device__ __align__(16) __half g_B3T[NG * MODES];    // [n][mode]  inverse op, c[k] folded
__device__ __align__(16) __half g_Xh[RROWS * NG];     // [r][n]
__device__ __align__(16) __half g_C2t[RROWS * MODES]; // [r][k]
__device__ float g_C1[MODES * RROWS];                 // [k][r] fp32
__device__ float g_C2[MODES * RROWS];                 // [k][r] fp32
__device__ float g_Wt[MODES * RROWS];                 // [k][i*64+o] fp32

// ---------------------------------------------------------------------------
// cp.async helpers
// ---------------------------------------------------------------------------
__device__ __forceinline__ void cp_async16(void* smem, const void* gmem) {
    uint32_t s = (uint32_t)__cvta_generic_to_shared(smem);
    asm volatile("cp.async.cg.shared.global [%0], [%1], 16;\n" :: "r"(s), "l"(gmem));
}
#define CP_COMMIT() asm volatile("cp.async.commit_group;\n" ::: "memory")
#define CP_WAIT0()  asm volatile("cp.async.wait_group 0;\n" ::: "memory")

// ---------------------------------------------------------------------------
// MMA: m16n8k16 row.col f32.f16.f16.f32
// ---------------------------------------------------------------------------
#define MMA_F16(c, a, b)                                                        \
    asm volatile(                                                               \
        "mma.sync.aligned.m16n8k16.row.col.f32.f16.f16.f32 "                    \
        "{%0,%1,%2,%3},{%4,%5,%6,%7},{%8,%9},{%0,%1,%2,%3};\n"                  \
        : "+f"((c)[0]), "+f"((c)[1]), "+f"((c)[2]), "+f"((c)[3])                \
        : "r"((a)[0]), "r"((a)[1]), "r"((a)[2]), "r"((a)[3]),                   \
          "r"((b)[0]), "r"((b)[1]))

// ---------------------------------------------------------------------------
// Kernel 0: build both DCT-I operator matrices (fp16), transposed.
// ---------------------------------------------------------------------------
__global__ void init_M_kernel() {
    int idx = blockIdx.x * blockDim.x + threadIdx.x;
    if (idx >= MODES * NG) return;
    {   // B1T[k][n] = cos(pi*k*n/2047) * c[n]
        int k = idx / NG, n = idx - k * NG;
        int m = (n * k) % (2 * (NG - 1));
        float v = cospif((float)m * (1.0f / (float)(NG - 1)));
        float cn = (n == 0 || n == NG - 1) ? 1.0f : 2.0f;
        g_B1T[idx] = __float2half(v * cn);
    }
    {   // B3T[n][k] = cos(pi*k*n/2047) * c[k]
        int n = idx / MODES, k = idx - n * MODES;
        int m = (n * k) % (2 * (NG - 1));
        float v = cospif((float)m * (1.0f / (float)(NG - 1)));
        float ck = (k == 0) ? 1.0f : 2.0f;
        g_B3T[idx] = __float2half(v * ck);
    }
}

// ---------------------------------------------------------------------------
// Kernel 1: convert X to fp16
// ---------------------------------------------------------------------------
__global__ void convert_X_kernel(const float* __restrict__ x) {
    int idx = blockIdx.x * blockDim.x + threadIdx.x;   // one float4 per thread
    if (idx >= RROWS * NG / 4) return;
    float4 v = ((const float4*)x)[idx];
    union { __half h[4]; uint2 u; } p;
    p.h[0] = __float2half(v.x); p.h[1] = __float2half(v.y);
    p.h[2] = __float2half(v.z); p.h[3] = __float2half(v.w);
    *(uint2*)&g_Xh[idx * 4] = p.u;
}

// ---------------------------------------------------------------------------
// Kernel 2: transpose weights [i,o,k] -> Wt[k][i*64+o] (fp32, for mix)
// ---------------------------------------------------------------------------
__global__ void transpose_W_kernel(const float* __restrict__ w) {
    __shared__ float tile[32][33];
    int kBase = blockIdx.x * 32;
    int rBase = blockIdx.y * 32;
    int tx = threadIdx.x, ty = threadIdx.y;   // (32, 8)
#pragma unroll
    for (int j = 0; j < 32; j += 8)
        tile[ty + j][tx] = w[(rBase + ty + j) * MODES + kBase + tx];
    __syncthreads();
#pragma unroll
    for (int j = 0; j < 32; j += 8)
        g_Wt[(kBase + ty + j) * RROWS + rBase + tx] = tile[tx][ty + j];
}

// ---------------------------------------------------------------------------
// GEMM1: C1[k][r] = sum_n X[r][n] * B1[n][k]
//   M=4096(r), N=512(mode), K=2048(n). CTA 128x128, BK=32, 2-stage cp.async.
//   8 warps (2Mx4N), warp 64x32, 4x4 m16n8 tiles, fp16 MMA, fp32 accum.
//   Epilogue: smem-staged transpose -> C1[k][r] coalesced fp32.
// ---------------------------------------------------------------------------
__global__ __launch_bounds__(256, 2) void gemm1_mma() {
    __shared__ __align__(16) unsigned char s_raw[2 * 2 * 128 * SLD * 2];  // 40960 B
    __half* sA = (__half*)s_raw;                 // [2][128*SLD]
    __half* sB = sA + 2 * 128 * SLD;             // [2][128*SLD]

    int tid = (int)threadIdx.x;
    int bm = blockIdx.y * 128;   // r
    int bn = blockIdx.x * 128;   // mode
    int warp = tid >> 5, lane = tid & 31;
    int wm = warp >> 2, wn = warp & 3;
    int g = lane >> 2, t2 = (lane & 3) * 2;

    int ldRow[2], ldSeg[2];
#pragma unroll
    for (int l = 0; l < 2; l++) {
        int idx = tid + l * 256;
        ldRow[l] = idx >> 2;
        ldSeg[l] = (idx & 3) * 8;
    }

    float acc[4][4][4];
#pragma unroll
    for (int a = 0; a < 4; a++)
#pragma unroll
        for (int b = 0; b < 4; b++)
#pragma unroll
            for (int c = 0; c < 4; c++) acc[a][b][c] = 0.0f;

    const int NIT = NG / 32;   // 64

    // prologue: stage 0
#pragma unroll
    for (int l = 0; l < 2; l++) {
        cp_async16(&sA[ldRow[l] * SLD + ldSeg[l]], &g_Xh[(bm + ldRow[l]) * NG + ldSeg[l]]);
        cp_async16(&sB[ldRow[l] * SLD + ldSeg[l]], &g_B1T[(bn + ldRow[l]) * NG + ldSeg[l]]);
    }
    CP_COMMIT();

    for (int it = 0; it < NIT; it++) {
        int buf = it & 1;
        CP_WAIT0();
        __syncthreads();
        if (it + 1 < NIT) {
            int nbuf = (it + 1) & 1;
            int k0 = (it + 1) * 32;
#pragma unroll
            for (int l = 0; l < 2; l++) {
                cp_async16(&sA[nbuf * 128 * SLD + ldRow[l] * SLD + ldSeg[l]],
                           &g_Xh[(bm + ldRow[l]) * NG + k0 + ldSeg[l]]);
                cp_async16(&sB[nbuf * 128 * SLD + ldRow[l] * SLD + ldSeg[l]],
                           &g_B1T[(bn + ldRow[l]) * NG + k0 + ldSeg[l]]);
            }
            CP_COMMIT();
        }
        const __half* cA = sA + buf * 128 * SLD;
        const __half* cB = sB + buf * 128 * SLD;
#pragma unroll
        for (int ks = 0; ks < 2; ks++) {
            int ko = ks * 16 + t2;
            uint32_t a[4][4], b[4][2];
#pragma unroll
            for (int mi = 0; mi < 4; mi++) {
                int r0 = (wm * 64 + mi * 16 + g) * SLD;
                a[mi][0] = *(const uint32_t*)&cA[r0 + ko];
                a[mi][1] = *(const uint32_t*)&cA[r0 + 8 * SLD + ko];
                a[mi][2] = *(const uint32_t*)&cA[r0 + ko + 8];
                a[mi][3] = *(const uint32_t*)&cA[r0 + 8 * SLD + ko + 8];
            }
#pragma unroll
            for (int ni = 0; ni < 4; ni++) {
                int n0 = (wn * 32 + ni * 8 + g) * SLD;
                b[ni][0] = *(const uint32_t*)&cB[n0 + ko];
                b[ni][1] = *(const uint32_t*)&cB[n0 + ko + 8];
            }
#pragma unroll
            for (int mi = 0; mi < 4; mi++)
#pragma unroll
                for (int ni = 0; ni < 4; ni++)
                    MMA_F16(acc[mi][ni], a[mi], b[ni]);
        }
        __syncthreads();
    }

    // Epilogue: stage per r-half (64 rows), write C1[k][r] coalesced.
    float* cbuf = (float*)s_raw;   // 64 x 129 fp32 = 33024 B (fits)
#pragma unroll
    for (int half = 0; half < 2; half++) {
        if (wm == half) {
#pragma unroll
            for (int mi = 0; mi < 4; mi++)
#pragma unroll
                for (int ni = 0; ni < 4; ni++) {
                    int rl = mi * 16 + g;
                    int cl = wn * 32 + ni * 8 + t2;
                    cbuf[rl * 129 + cl]           = acc[mi][ni][0];
                    cbuf[rl * 129 + cl + 1]       = acc[mi][ni][1];
                    cbuf[(rl + 8) * 129 + cl]     = acc[mi][ni][2];
                    cbuf[(rl + 8) * 129 + cl + 1] = acc[mi][ni][3];
                }
        }
        __syncthreads();
#pragma unroll
        for (int p = 0; p < 32; p++) {
            int idx = tid + p * 256;           // 8192 = 128k x 64r
            int kc = idx >> 6;
            int r = idx & 63;
            g_C1[(bn + kc) * RROWS + bm + half * 64 + r] = cbuf[r * 129 + kc];
        }
        __syncthreads();
    }
}

// ---------------------------------------------------------------------------
// Kernel: per-mode channel mixing (fp32 SIMT; 0.13 GMAC).
// ---------------------------------------------------------------------------
__global__ __launch_bounds__(256) void mix_kernel() {
    int k = blockIdx.x;
    __shared__ float As[64][65];
    __shared__ float Ws[64][65];
    const float* a = &g_C1[k * RROWS];
    const float* w = &g_Wt[k * RROWS];
    int tid = (int)threadIdx.x;
#pragma unroll
    for (int l = 0; l < 16; l++) {
        int idx = tid + l * 256;
        int r = idx >> 6, c = idx & 63;
        As[r][c] = a[idx];
        Ws[r][c] = w[idx];
    }
    __syncthreads();

    int tx = tid & 15, ty = tid >> 4;
    float acc[4][4];
#pragma unroll
    for (int p = 0; p < 4; p++)
#pragma unroll
        for (int q = 0; q < 4; q++) acc[p][q] = 0.0f;

#pragma unroll 8
    for (int i = 0; i < 64; i++) {
        float av[4], wv[4];
#pragma unroll
        for (int p = 0; p < 4; p++) av[p] = As[ty * 4 + p][i];
#pragma unroll
        for (int q = 0; q < 4; q++) wv[q] = Ws[i][tx * 4 + q];
#pragma unroll
        for (int p = 0; p < 4; p++)
#pragma unroll
            for (int q = 0; q < 4; q++) acc[p][q] += av[p] * wv[q];
    }

    float* c2 = &g_C2[k * RROWS];
#pragma unroll
    for (int p = 0; p < 4; p++) {
        float4 v = make_float4(acc[p][0], acc[p][1], acc[p][2], acc[p][3]);
        *(float4*)&c2[(ty * 4 + p) * 64 + tx * 4] = v;
    }
}

// ---------------------------------------------------------------------------
// Kernel: transpose C2 [k][r] fp32 -> C2t [r][k] fp16
// ---------------------------------------------------------------------------
__global__ void transpose_C2_kernel() {
    __shared__ float tile[32][33];
    int k0 = blockIdx.x * 32;
    int r0 = blockIdx.y * 32;
    int tx = threadIdx.x, ty = threadIdx.y;   // (32, 8)
#pragma unroll
    for (int j = 0; j < 32; j += 8)
        tile[ty + j][tx] = g_C2[(k0 + ty + j) * RROWS + r0 + tx];
    __syncthreads();
#pragma unroll
    for (int j = 0; j < 32; j += 8)
        g_C2t[(r0 + ty + j) * MODES + k0 + tx] = __float2half(tile[tx][ty + j]);
}

// ---------------------------------------------------------------------------
// GEMM3: out[r][n] = sum_k C2t[r][k] * B3[k][n]
//   M=4096(r), N=2048(n), K=512(mode). Same pipelined structure, direct store.
// ---------------------------------------------------------------------------
__global__ __launch_bounds__(256, 2) void gemm3_mma(float* __restrict__ out) {
    __shared__ __align__(16) unsigned char s_raw[2 * 2 * 128 * SLD * 2];
    __half* sA = (__half*)s_raw;
    __half* sB = sA + 2 * 128 * SLD;

    int tid = (int)threadIdx.x;
    int bm = blockIdx.y * 128;   // r
    int bn = blockIdx.x * 128;   // grid n
    int warp = tid >> 5, lane = tid & 31;
    int wm = warp >> 2, wn = warp & 3;
    int g = lane >> 2, t2 = (lane & 3) * 2;

    int ldRow[2], ldSeg[2];
#pragma unroll
    for (int l = 0; l < 2; l++) {
        int idx = tid + l * 256;
        ldRow[l] = idx >> 2;
        ldSeg[l] = (idx & 3) * 8;
    }

    float acc[4][4][4];
#pragma unroll
    for (int a = 0; a < 4; a++)
#pragma unroll
        for (int b = 0; b < 4; b++)
#pragma unroll
            for (int c = 0; c < 4; c++) acc[a][b][c] = 0.0f;

    const int NIT = MODES / 32;  // 16

#pragma unroll
    for (int l = 0; l < 2; l++) {
        cp_async16(&sA[ldRow[l] * SLD + ldSeg[l]], &g_C2t[(bm + ldRow[l]) * MODES + ldSeg[l]]);
        cp_async16(&sB[ldRow[l] * SLD + ldSeg[l]], &g_B3T[(bn + ldRow[l]) * MODES + ldSeg[l]]);
    }
    CP_COMMIT();

    for (int it = 0; it < NIT; it++) {
        int buf = it & 1;
        CP_WAIT0();
        __syncthreads();
        if (it + 1 < NIT) {
            int nbuf = (it + 1) & 1;
            int k0 = (it + 1) * 32;
#pragma unroll
            for (int l = 0; l < 2; l++) {
                cp_async16(&sA[nbuf * 128 * SLD + ldRow[l] * SLD + ldSeg[l]],
                           &g_C2t[(bm + ldRow[l]) * MODES + k0 + ldSeg[l]]);
                cp_async16(&sB[nbuf * 128 * SLD + ldRow[l] * SLD + ldSeg[l]],
                           &g_B3T[(bn + ldRow[l]) * MODES + k0 + ldSeg[l]]);
            }
            CP_COMMIT();
        }
        const __half* cA = sA + buf * 128 * SLD;
        const __half* cB = sB + buf * 128 * SLD;
#pragma unroll
        for (int ks = 0; ks < 2; ks++) {
            int ko = ks * 16 + t2;
            uint32_t a[4][4], b[4][2];
#pragma unroll
            for (int mi = 0; mi < 4; mi++) {
                int r0 = (wm * 64 + mi * 16 + g) * SLD;
                a[mi][0] = *(const uint32_t*)&cA[r0 + ko];
                a[mi][1] = *(const uint32_t*)&cA[r0 + 8 * SLD + ko];
                a[mi][2] = *(const uint32_t*)&cA[r0 + ko + 8];
                a[mi][3] = *(const uint32_t*)&cA[r0 + 8 * SLD + ko + 8];
            }
#pragma unroll
            for (int ni = 0; ni < 4; ni++) {
                int n0 = (wn * 32 + ni * 8 + g) * SLD;
                b[ni][0] = *(const uint32_t*)&cB[n0 + ko];
                b[ni][1] = *(const uint32_t*)&cB[n0 + ko + 8];
            }
#pragma unroll
            for (int mi = 0; mi < 4; mi++)
#pragma unroll
                for (int ni = 0; ni < 4; ni++)
                    MMA_F16(acc[mi][ni], a[mi], b[ni]);
        }
        __syncthreads();
    }

    // Direct store: contiguous float2 per c-pair.
#pragma unroll
    for (int mi = 0; mi < 4; mi++)
#pragma unroll
        for (int ni = 0; ni < 4; ni++) {
            int row = bm + wm * 64 + mi * 16 + g;
            int col = bn + wn * 32 + ni * 8 + t2;
            float2 v0 = make_float2(acc[mi][ni][0], acc[mi][ni][1]);
            float2 v1 = make_float2(acc[mi][ni][2], acc[mi][ni][3]);
            *(float2*)&out[row * NG + col] = v0;
            *(float2*)&out[(row + 8) * NG + col] = v1;
        }
}

// ---------------------------------------------------------------------------
// Launch
// ---------------------------------------------------------------------------
extern "C" void kernel_launch(void* const* d_in, const int* in_sizes, int n_in,
                              void* d_out, int out_size) {
    const float* x = (const float*)d_in[0];   // [64, 64, 2048] f32
    const float* w = (const float*)d_in[1];   // [64, 64, 512]  f32
    float* out = (float*)d_out;               // [64, 64, 2048] f32

    init_M_kernel<<<(MODES * NG + 255) / 256, 256>>>();
    convert_X_kernel<<<(RROWS * NG / 4 + 255) / 256, 256>>>(x);
    transpose_W_kernel<<<dim3(MODES / 32, RROWS / 32), dim3(32, 8)>>>(w);
    gemm1_mma<<<dim3(MODES / 128, RROWS / 128), 256>>>();
    mix_kernel<<<MODES, 256>>>();
    transpose_C2_kernel<<<dim3(MODES / 32, RROWS / 32), dim3(32, 8)>>>();
    gemm3_mma<<<dim3(NG / 128, RROWS / 128), 256>>>(out);
}

// round 4
// speedup vs baseline: 4.2389x; 1.1256x over previous
#include <cuda_runtime.h>
#include <cuda_fp16.h>
#include <stdint.h>

#define BB      64
#define NG      2048
#define MODES   512
#define RROWS   4096
#define SLD     40          // padded smem row stride (half); 80B rows -> ldmatrix conflict-free
#define STG_B   (2 * 128 * SLD * 2)   // bytes per pipeline stage (A+B): 20480
#define NSTG    4

// ---------------------------------------------------------------------------
// Static device scratch
// ---------------------------------------------------------------------------
__device__ float g_cosTab[2 * (NG - 1)];              // 4094 distinct cos values
__device__ __align__(16) __half g_B1T[MODES * NG];    // [mode][n]  forward op, c[n] folded
__device__ __align__(16) __half g_B3T[NG * MODES];    // [n][mode]  inverse op, c[k] folded
__device__ __align__(16) __half g_Xh[RROWS * NG];     // [r][n]
__device__ __align__(16) __half g_C2h[MODES * RROWS]; // [k][r] fp16 (mix output)
__device__ __align__(16) __half g_C2t[RROWS * MODES]; // [r][k] fp16
__device__ float g_C1[MODES * RROWS];                 // [k][r] fp32
__device__ float g_Wt[MODES * RROWS];                 // [k][i*64+o] fp32

// ---------------------------------------------------------------------------
// Async-copy / MMA / ldmatrix helpers
// ---------------------------------------------------------------------------
__device__ __forceinline__ void cp_async16(void* smem, const void* gmem) {
    uint32_t s = (uint32_t)__cvta_generic_to_shared(smem);
    asm volatile("cp.async.cg.shared.global [%0], [%1], 16;\n" :: "r"(s), "l"(gmem));
}
#define CP_COMMIT() asm volatile("cp.async.commit_group;\n" ::: "memory")
#define CP_WAIT(n)  asm volatile("cp.async.wait_group %0;\n" :: "n"(n) : "memory")

#define MMA_F16(c, a, b)                                                        \
    asm volatile(                                                               \
        "mma.sync.aligned.m16n8k16.row.col.f32.f16.f16.f32 "                    \
        "{%0,%1,%2,%3},{%4,%5,%6,%7},{%8,%9},{%0,%1,%2,%3};\n"                  \
        : "+f"((c)[0]), "+f"((c)[1]), "+f"((c)[2]), "+f"((c)[3])                \
        : "r"((a)[0]), "r"((a)[1]), "r"((a)[2]), "r"((a)[3]),                   \
          "r"((b)[0]), "r"((b)[1]))

__device__ __forceinline__ void ldsm_x4(uint32_t& r0, uint32_t& r1, uint32_t& r2,
                                        uint32_t& r3, uint32_t saddr) {
    asm volatile("ldmatrix.sync.aligned.m8n8.x4.shared.b16 {%0,%1,%2,%3}, [%4];"
                 : "=r"(r0), "=r"(r1), "=r"(r2), "=r"(r3) : "r"(saddr));
}

// ---------------------------------------------------------------------------
// Kernel: cos table (4094 distinct values of cos(pi*m/2047))
// ---------------------------------------------------------------------------
__global__ void init_table_kernel() {
    int i = blockIdx.x * blockDim.x + threadIdx.x;
    if (i < 2 * (NG - 1))
        g_cosTab[i] = cospif((float)i * (1.0f / (float)(NG - 1)));
}

// ---------------------------------------------------------------------------
// Kernel: build DCT-I operators (fp16, transposed) via table gather
// ---------------------------------------------------------------------------
__global__ void init_M_kernel() {
    int idx = blockIdx.x * blockDim.x + threadIdx.x;
    if (idx >= MODES * NG) return;
    {   // B1T[k][n] = cos(pi*k*n/2047) * c[n]
        int k = idx / NG, n = idx - k * NG;
        float v = g_cosTab[(n * k) % (2 * (NG - 1))];
        float cn = (n == 0 || n == NG - 1) ? 1.0f : 2.0f;
        g_B1T[idx] = __float2half(v * cn);
    }
    {   // B3T[n][k] = cos(pi*k*n/2047) * c[k]
        int n = idx / MODES, k = idx - n * MODES;
        float v = g_cosTab[(n * k) % (2 * (NG - 1))];
        float ck = (k == 0) ? 1.0f : 2.0f;
        g_B3T[idx] = __float2half(v * ck);
    }
}

// ---------------------------------------------------------------------------
// Kernel: convert X to fp16
// ---------------------------------------------------------------------------
__global__ void convert_X_kernel(const float* __restrict__ x) {
    int idx = blockIdx.x * blockDim.x + threadIdx.x;
    if (idx >= RROWS * NG / 4) return;
    float4 v = ((const float4*)x)[idx];
    union { __half h[4]; uint2 u; } p;
    p.h[0] = __float2half(v.x); p.h[1] = __float2half(v.y);
    p.h[2] = __float2half(v.z); p.h[3] = __float2half(v.w);
    *(uint2*)&g_Xh[idx * 4] = p.u;
}

// ---------------------------------------------------------------------------
// Kernel: transpose weights [i,o,k] -> Wt[k][i*64+o] (fp32, for mix)
// ---------------------------------------------------------------------------
__global__ void transpose_W_kernel(const float* __restrict__ w) {
    __shared__ float tile[32][33];
    int kBase = blockIdx.x * 32;
    int rBase = blockIdx.y * 32;
    int tx = threadIdx.x, ty = threadIdx.y;   // (32, 8)
#pragma unroll
    for (int j = 0; j < 32; j += 8)
        tile[ty + j][tx] = w[(rBase + ty + j) * MODES + kBase + tx];
    __syncthreads();
#pragma unroll
    for (int j = 0; j < 32; j += 8)
        g_Wt[(kBase + ty + j) * RROWS + rBase + tx] = tile[tx][ty + j];
}

// ---------------------------------------------------------------------------
// GEMM1: C1[k][r] = sum_n X[r][n] * B1[n][k]
//   M=4096(r), N=512(mode), K=2048(n). CTA 128x128, BK=32, 4-stage cp.async,
//   ldmatrix fragment loads. Epilogue: smem transpose -> C1[k][r] fp32.
// ---------------------------------------------------------------------------
extern __shared__ __align__(16) unsigned char dsm[];

__global__ __launch_bounds__(256, 1) void gemm1_mma() {
    int tid = (int)threadIdx.x;
    int bm = blockIdx.y * 128;   // r
    int bn = blockIdx.x * 128;   // mode
    int warp = tid >> 5, lane = tid & 31;
    int wm = warp >> 2, wn = warp & 3;
    int g = lane >> 2, t2 = (lane & 3) * 2;

    uint32_t sbase = (uint32_t)__cvta_generic_to_shared(dsm);

    int ldRow[2], ldSeg[2];
#pragma unroll
    for (int l = 0; l < 2; l++) {
        int idx = tid + l * 256;
        ldRow[l] = idx >> 2;
        ldSeg[l] = (idx & 3) * 8;
    }

    // per-lane ldmatrix byte offsets (within a stage)
    uint32_t aoff[4], boff[2];
#pragma unroll
    for (int mi = 0; mi < 4; mi++)
        aoff[mi] = ((wm * 64 + mi * 16 + (lane & 15)) * SLD + ((lane >> 4) << 3)) * 2;
#pragma unroll
    for (int nq = 0; nq < 2; nq++)
        boff[nq] = (uint32_t)(128 * SLD * 2) +
                   ((wn * 32 + nq * 16 + (lane & 7) + ((lane >> 4) << 3)) * SLD +
                    (((lane >> 3) & 1) << 3)) * 2;

    float acc[4][4][4];
#pragma unroll
    for (int a = 0; a < 4; a++)
#pragma unroll
        for (int b = 0; b < 4; b++)
#pragma unroll
            for (int c = 0; c < 4; c++) acc[a][b][c] = 0.0f;

    const int NIT = NG / 32;   // 64

    // prologue: stages 0..2
#pragma unroll
    for (int s = 0; s < 3; s++) {
        unsigned char* st = dsm + s * STG_B;
        __half* sA = (__half*)st;
        __half* sB = sA + 128 * SLD;
        int k0 = s * 32;
#pragma unroll
        for (int l = 0; l < 2; l++) {
            cp_async16(&sA[ldRow[l] * SLD + ldSeg[l]], &g_Xh[(bm + ldRow[l]) * NG + k0 + ldSeg[l]]);
            cp_async16(&sB[ldRow[l] * SLD + ldSeg[l]], &g_B1T[(bn + ldRow[l]) * NG + k0 + ldSeg[l]]);
        }
        CP_COMMIT();
    }

    for (int it = 0; it < NIT; it++) {
        CP_WAIT(2);
        __syncthreads();
        if (it + 3 < NIT) {
            int s = (it + 3) & 3;
            int k0 = (it + 3) * 32;
            unsigned char* st = dsm + s * STG_B;
            __half* sA = (__half*)st;
            __half* sB = sA + 128 * SLD;
#pragma unroll
            for (int l = 0; l < 2; l++) {
                cp_async16(&sA[ldRow[l] * SLD + ldSeg[l]], &g_Xh[(bm + ldRow[l]) * NG + k0 + ldSeg[l]]);
                cp_async16(&sB[ldRow[l] * SLD + ldSeg[l]], &g_B1T[(bn + ldRow[l]) * NG + k0 + ldSeg[l]]);
            }
            CP_COMMIT();
        }
        uint32_t stg = sbase + (uint32_t)((it & 3) * STG_B);
#pragma unroll
        for (int ks = 0; ks < 2; ks++) {
            uint32_t kb = (uint32_t)(ks * 32);
            uint32_t a[4][4], b[4][2];
#pragma unroll
            for (int mi = 0; mi < 4; mi++)
                ldsm_x4(a[mi][0], a[mi][1], a[mi][2], a[mi][3], stg + aoff[mi] + kb);
#pragma unroll
            for (int nq = 0; nq < 2; nq++)
                ldsm_x4(b[nq * 2][0], b[nq * 2][1], b[nq * 2 + 1][0], b[nq * 2 + 1][1],
                        stg + boff[nq] + kb);
#pragma unroll
            for (int mi = 0; mi < 4; mi++)
#pragma unroll
                for (int ni = 0; ni < 4; ni++)
                    MMA_F16(acc[mi][ni], a[mi], b[ni]);
        }
    }
    __syncthreads();

    // Epilogue: stage per r-half (64 rows), write C1[k][r] coalesced fp32.
    float* cbuf = (float*)dsm;   // 64 x 129 fp32 = 33024 B (fits in 80KB)
#pragma unroll
    for (int half = 0; half < 2; half++) {
        if (wm == half) {
#pragma unroll
            for (int mi = 0; mi < 4; mi++)
#pragma unroll
                for (int ni = 0; ni < 4; ni++) {
                    int rl = mi * 16 + g;
                    int cl = wn * 32 + ni * 8 + t2;
                    cbuf[rl * 129 + cl]           = acc[mi][ni][0];
                    cbuf[rl * 129 + cl + 1]       = acc[mi][ni][1];
                    cbuf[(rl + 8) * 129 + cl]     = acc[mi][ni][2];
                    cbuf[(rl + 8) * 129 + cl + 1] = acc[mi][ni][3];
                }
        }
        __syncthreads();
#pragma unroll
        for (int p = 0; p < 32; p++) {
            int idx = tid + p * 256;           // 8192 = 128k x 64r
            int kc = idx >> 6;
            int r = idx & 63;
            g_C1[(bn + kc) * RROWS + bm + half * 64 + r] = cbuf[r * 129 + kc];
        }
        __syncthreads();
    }
}

// ---------------------------------------------------------------------------
// Kernel: per-mode channel mixing (fp32 SIMT), fp16 output C2h[k][r].
// ---------------------------------------------------------------------------
__global__ __launch_bounds__(256) void mix_kernel() {
    int k = blockIdx.x;
    __shared__ float As[64][65];
    __shared__ float Ws[64][65];
    const float* a = &g_C1[k * RROWS];
    const float* w = &g_Wt[k * RROWS];
    int tid = (int)threadIdx.x;
#pragma unroll
    for (int l = 0; l < 16; l++) {
        int idx = tid + l * 256;
        int r = idx >> 6, c = idx & 63;
        As[r][c] = a[idx];
        Ws[r][c] = w[idx];
    }
    __syncthreads();

    int tx = tid & 15, ty = tid >> 4;
    float acc[4][4];
#pragma unroll
    for (int p = 0; p < 4; p++)
#pragma unroll
        for (int q = 0; q < 4; q++) acc[p][q] = 0.0f;

#pragma unroll 8
    for (int i = 0; i < 64; i++) {
        float av[4], wv[4];
#pragma unroll
        for (int p = 0; p < 4; p++) av[p] = As[ty * 4 + p][i];
#pragma unroll
        for (int q = 0; q < 4; q++) wv[q] = Ws[i][tx * 4 + q];
#pragma unroll
        for (int p = 0; p < 4; p++)
#pragma unroll
            for (int q = 0; q < 4; q++) acc[p][q] += av[p] * wv[q];
    }

    __half* c2 = &g_C2h[k * RROWS];
#pragma unroll
    for (int p = 0; p < 4; p++) {
        union { __half2 h2[2]; uint2 u; } pk;
        pk.h2[0] = __floats2half2_rn(acc[p][0], acc[p][1]);
        pk.h2[1] = __floats2half2_rn(acc[p][2], acc[p][3]);
        *(uint2*)&c2[(ty * 4 + p) * 64 + tx * 4] = pk.u;
    }
}

// ---------------------------------------------------------------------------
// Kernel: transpose C2h [k][r] fp16 -> C2t [r][k] fp16
// ---------------------------------------------------------------------------
__global__ void transpose_C2_kernel() {
    __shared__ __half tile[32][33];
    int k0 = blockIdx.x * 32;
    int r0 = blockIdx.y * 32;
    int tx = threadIdx.x, ty = threadIdx.y;   // (32, 8)
#pragma unroll
    for (int j = 0; j < 32; j += 8)
        tile[ty + j][tx] = g_C2h[(k0 + ty + j) * RROWS + r0 + tx];
    __syncthreads();
#pragma unroll
    for (int j = 0; j < 32; j += 8)
        g_C2t[(r0 + ty + j) * MODES + k0 + tx] = tile[tx][ty + j];
}

// ---------------------------------------------------------------------------
// GEMM3: out[r][n] = sum_k C2t[r][k] * B3[k][n]
//   M=4096(r), N=2048(n), K=512(mode). Same pipelined ldmatrix structure.
// ---------------------------------------------------------------------------
__global__ __launch_bounds__(256, 2) void gemm3_mma(float* __restrict__ out) {
    int tid = (int)threadIdx.x;
    int bm = blockIdx.y * 128;   // r
    int bn = blockIdx.x * 128;   // grid n
    int warp = tid >> 5, lane = tid & 31;
    int wm = warp >> 2, wn = warp & 3;
    int g = lane >> 2, t2 = (lane & 3) * 2;

    uint32_t sbase = (uint32_t)__cvta_generic_to_shared(dsm);

    int ldRow[2], ldSeg[2];
#pragma unroll
    for (int l = 0; l < 2; l++) {
        int idx = tid + l * 256;
        ldRow[l] = idx >> 2;
        ldSeg[l] = (idx & 3) * 8;
    }

    uint32_t aoff[4], boff[2];
#pragma unroll
    for (int mi = 0; mi < 4; mi++)
        aoff[mi] = ((wm * 64 + mi * 16 + (lane & 15)) * SLD + ((lane >> 4) << 3)) * 2;
#pragma unroll
    for (int nq = 0; nq < 2; nq++)
        boff[nq] = (uint32_t)(128 * SLD * 2) +
                   ((wn * 32 + nq * 16 + (lane & 7) + ((lane >> 4) << 3)) * SLD +
                    (((lane >> 3) & 1) << 3)) * 2;

    float acc[4][4][4];
#pragma unroll
    for (int a = 0; a < 4; a++)
#pragma unroll
        for (int b = 0; b < 4; b++)
#pragma unroll
            for (int c = 0; c < 4; c++) acc[a][b][c] = 0.0f;

    const int NIT = MODES / 32;  // 16

#pragma unroll
    for (int s = 0; s < 3; s++) {
        unsigned char* st = dsm + s * STG_B;
        __half* sA = (__half*)st;
        __half* sB = sA + 128 * SLD;
        int k0 = s * 32;
#pragma unroll
        for (int l = 0; l < 2; l++) {
            cp_async16(&sA[ldRow[l] * SLD + ldSeg[l]], &g_C2t[(bm + ldRow[l]) * MODES + k0 + ldSeg[l]]);
            cp_async16(&sB[ldRow[l] * SLD + ldSeg[l]], &g_B3T[(bn + ldRow[l]) * MODES + k0 + ldSeg[l]]);
        }
        CP_COMMIT();
    }

    for (int it = 0; it < NIT; it++) {
        CP_WAIT(2);
        __syncthreads();
        if (it + 3 < NIT) {
            int s = (it + 3) & 3;
            int k0 = (it + 3) * 32;
            unsigned char* st = dsm + s * STG_B;
            __half* sA = (__half*)st;
            __half* sB = sA + 128 * SLD;
#pragma unroll
            for (int l = 0; l < 2; l++) {
                cp_async16(&sA[ldRow[l] * SLD + ldSeg[l]], &g_C2t[(bm + ldRow[l]) * MODES + k0 + ldSeg[l]]);
                cp_async16(&sB[ldRow[l] * SLD + ldSeg[l]], &g_B3T[(bn + ldRow[l]) * MODES + k0 + ldSeg[l]]);
            }
            CP_COMMIT();
        }
        uint32_t stg = sbase + (uint32_t)((it & 3) * STG_B);
#pragma unroll
        for (int ks = 0; ks < 2; ks++) {
            uint32_t kb = (uint32_t)(ks * 32);
            uint32_t a[4][4], b[4][2];
#pragma unroll
            for (int mi = 0; mi < 4; mi++)
                ldsm_x4(a[mi][0], a[mi][1], a[mi][2], a[mi][3], stg + aoff[mi] + kb);
#pragma unroll
            for (int nq = 0; nq < 2; nq++)
                ldsm_x4(b[nq * 2][0], b[nq * 2][1], b[nq * 2 + 1][0], b[nq * 2 + 1][1],
                        stg + boff[nq] + kb);
#pragma unroll
            for (int mi = 0; mi < 4; mi++)
#pragma unroll
                for (int ni = 0; ni < 4; ni++)
                    MMA_F16(acc[mi][ni], a[mi], b[ni]);
        }
    }

    // Direct store: contiguous float2 per c-pair.
#pragma unroll
    for (int mi = 0; mi < 4; mi++)
#pragma unroll
        for (int ni = 0; ni < 4; ni++) {
            int row = bm + wm * 64 + mi * 16 + g;
            int col = bn + wn * 32 + ni * 8 + t2;
            float2 v0 = make_float2(acc[mi][ni][0], acc[mi][ni][1]);
            float2 v1 = make_float2(acc[mi][ni][2], acc[mi][ni][3]);
            *(float2*)&out[row * NG + col] = v0;
            *(float2*)&out[(row + 8) * NG + col] = v1;
        }
}

// ---------------------------------------------------------------------------
// Launch
// ---------------------------------------------------------------------------
extern "C" void kernel_launch(void* const* d_in, const int* in_sizes, int n_in,
                              void* d_out, int out_size) {
    const float* x = (const float*)d_in[0];   // [64, 64, 2048] f32
    const float* w = (const float*)d_in[1];   // [64, 64, 512]  f32
    float* out = (float*)d_out;               // [64, 64, 2048] f32

    cudaFuncSetAttribute(gemm1_mma, cudaFuncAttributeMaxDynamicSharedMemorySize, NSTG * STG_B);
    cudaFuncSetAttribute(gemm3_mma, cudaFuncAttributeMaxDynamicSharedMemorySize, NSTG * STG_B);

    init_table_kernel<<<16, 256>>>();
    init_M_kernel<<<(MODES * NG + 255) / 256, 256>>>();
    convert_X_kernel<<<(RROWS * NG / 4 + 255) / 256, 256>>>(x);
    transpose_W_kernel<<<dim3(MODES / 32, RROWS / 32), dim3(32, 8)>>>(w);
    gemm1_mma<<<dim3(MODES / 128, RROWS / 128), 256, NSTG * STG_B>>>();
    mix_kernel<<<MODES, 256>>>();
    transpose_C2_kernel<<<dim3(MODES / 32, RROWS / 32), dim3(32, 8)>>>();
    gemm3_mma<<<dim3(NG / 128, RROWS / 128), 256, NSTG * STG_B>>>(out);
}

// round 5
// speedup vs baseline: 4.3198x; 1.0191x over previous
#include <cuda_runtime.h>
#include <cuda_fp16.h>
#include <stdint.h>

#define BB      64
#define NG      2048
#define MODES   512
#define RROWS   4096
#define SLD     40                        // padded smem row stride (half); conflict-free ldmatrix
#define SLDE    136                       // epilogue cbuf stride (half)
#define STG1_B  ((128 + 64) * SLD * 2)    // gemm1 stage bytes: 15360
#define STG3_B  (2 * 128 * SLD * 2)       // gemm3 stage bytes: 20480
#define NSTG    4

// ---------------------------------------------------------------------------
// Static device scratch
// ---------------------------------------------------------------------------
__device__ float g_cosTab[2 * (NG - 1)];
__device__ __align__(16) __half g_B1T[MODES * NG];     // [mode][n]  forward op, c[n] folded
__device__ __align__(16) __half g_B3T[NG * MODES];     // [n][mode]  inverse op, c[k] folded
__device__ __align__(16) __half g_Xh[RROWS * NG];      // [r][n]
__device__ __align__(16) __half g_C1h[MODES * RROWS];  // [k][r] fp16 (gemm1 out)
__device__ __align__(16) __half g_Wt16[MODES * RROWS]; // [k][i*64+o] fp16
__device__ __align__(16) __half g_C2h[MODES * RROWS];  // [k][r] fp16 (mix out)
__device__ __align__(16) __half g_C2t[RROWS * MODES];  // [r][k] fp16

// ---------------------------------------------------------------------------
// Async-copy / MMA / ldmatrix helpers
// ---------------------------------------------------------------------------
__device__ __forceinline__ void cp_async16(void* smem, const void* gmem) {
    uint32_t s = (uint32_t)__cvta_generic_to_shared(smem);
    asm volatile("cp.async.cg.shared.global [%0], [%1], 16;\n" :: "r"(s), "l"(gmem));
}
#define CP_COMMIT() asm volatile("cp.async.commit_group;\n" ::: "memory")
#define CP_WAIT(n)  asm volatile("cp.async.wait_group %0;\n" :: "n"(n) : "memory")

#define MMA_F16(c, a, b)                                                        \
    asm volatile(                                                               \
        "mma.sync.aligned.m16n8k16.row.col.f32.f16.f16.f32 "                    \
        "{%0,%1,%2,%3},{%4,%5,%6,%7},{%8,%9},{%0,%1,%2,%3};\n"                  \
        : "+f"((c)[0]), "+f"((c)[1]), "+f"((c)[2]), "+f"((c)[3])                \
        : "r"((a)[0]), "r"((a)[1]), "r"((a)[2]), "r"((a)[3]),                   \
          "r"((b)[0]), "r"((b)[1]))

__device__ __forceinline__ void ldsm_x4(uint32_t& r0, uint32_t& r1, uint32_t& r2,
                                        uint32_t& r3, uint32_t saddr) {
    asm volatile("ldmatrix.sync.aligned.m8n8.x4.shared.b16 {%0,%1,%2,%3}, [%4];"
                 : "=r"(r0), "=r"(r1), "=r"(r2), "=r"(r3) : "r"(saddr));
}
__device__ __forceinline__ void ldsm_x4_t(uint32_t& r0, uint32_t& r1, uint32_t& r2,
                                          uint32_t& r3, uint32_t saddr) {
    asm volatile("ldmatrix.sync.aligned.m8n8.x4.trans.shared.b16 {%0,%1,%2,%3}, [%4];"
                 : "=r"(r0), "=r"(r1), "=r"(r2), "=r"(r3) : "r"(saddr));
}

// ---------------------------------------------------------------------------
// Init kernels
// ---------------------------------------------------------------------------
__global__ void init_table_kernel() {
    int i = blockIdx.x * blockDim.x + threadIdx.x;
    if (i < 2 * (NG - 1))
        g_cosTab[i] = cospif((float)i * (1.0f / (float)(NG - 1)));
}

__global__ void init_M_kernel() {
    int idx = blockIdx.x * blockDim.x + threadIdx.x;
    if (idx >= MODES * NG) return;
    {   // B1T[k][n] = cos(pi*k*n/2047) * c[n]
        int k = idx / NG, n = idx - k * NG;
        float v = g_cosTab[(n * k) % (2 * (NG - 1))];
        float cn = (n == 0 || n == NG - 1) ? 1.0f : 2.0f;
        g_B1T[idx] = __float2half(v * cn);
    }
    {   // B3T[n][k] = cos(pi*k*n/2047) * c[k]
        int n = idx / MODES, k = idx - n * MODES;
        float v = g_cosTab[(n * k) % (2 * (NG - 1))];
        float ck = (k == 0) ? 1.0f : 2.0f;
        g_B3T[idx] = __float2half(v * ck);
    }
}

__global__ void convert_X_kernel(const float* __restrict__ x) {
    int idx = blockIdx.x * blockDim.x + threadIdx.x;
    if (idx >= RROWS * NG / 4) return;
    float4 v = ((const float4*)x)[idx];
    union { __half h[4]; uint2 u; } p;
    p.h[0] = __float2half(v.x); p.h[1] = __float2half(v.y);
    p.h[2] = __float2half(v.z); p.h[3] = __float2half(v.w);
    *(uint2*)&g_Xh[idx * 4] = p.u;
}

// transpose weights [i,o,k] f32 -> Wt16[k][i*64+o] fp16
__global__ void transpose_W_kernel(const float* __restrict__ w) {
    __shared__ float tile[32][33];
    int kBase = blockIdx.x * 32;
    int rBase = blockIdx.y * 32;
    int tx = threadIdx.x, ty = threadIdx.y;   // (32, 8)
#pragma unroll
    for (int j = 0; j < 32; j += 8)
        tile[ty + j][tx] = w[(rBase + ty + j) * MODES + kBase + tx];
    __syncthreads();
#pragma unroll
    for (int j = 0; j < 32; j += 8)
        g_Wt16[(kBase + ty + j) * RROWS + rBase + tx] = __float2half(tile[tx][ty + j]);
}

// ---------------------------------------------------------------------------
// GEMM1: C1h[k][r] = sum_n X[r][n] * B1[n][k]   (fp16 out)
//   M=4096(r), N=512(mode), K=2048(n). CTA 128m x 64n, BK=32, 4-stage cp.async,
//   grid 256, 2 CTAs/SM. 8 warps = 2M x 4N, warp 64x16, acc 4x2 m16n8.
// ---------------------------------------------------------------------------
extern __shared__ __align__(16) unsigned char dsm[];

__global__ __launch_bounds__(256, 2) void gemm1_mma() {
    int tid = (int)threadIdx.x;
    int bm = blockIdx.y * 128;   // r
    int bn = blockIdx.x * 64;    // mode
    int warp = tid >> 5, lane = tid & 31;
    int wm = warp >> 2, wn = warp & 3;
    int g = lane >> 2, t2 = (lane & 3) * 2;

    uint32_t sbase = (uint32_t)__cvta_generic_to_shared(dsm);

    // A loads: 128x32 halves = 512 uint4 (2/thread); B: 64x32 = 256 uint4 (1/thread)
    int aRow[2], aSeg[2];
#pragma unroll
    for (int l = 0; l < 2; l++) {
        int idx = tid + l * 256;
        aRow[l] = idx >> 2;
        aSeg[l] = (idx & 3) * 8;
    }
    int bRow = tid >> 2, bSeg = (tid & 3) * 8;

    uint32_t aoff[4];
#pragma unroll
    for (int mi = 0; mi < 4; mi++)
        aoff[mi] = ((wm * 64 + mi * 16 + (lane & 15)) * SLD + ((lane >> 4) << 3)) * 2;
    uint32_t boff = (uint32_t)(128 * SLD * 2) +
                    ((wn * 16 + (lane & 7) + ((lane >> 4) << 3)) * SLD +
                     (((lane >> 3) & 1) << 3)) * 2;

    float acc[4][2][4];
#pragma unroll
    for (int a = 0; a < 4; a++)
#pragma unroll
        for (int b = 0; b < 2; b++)
#pragma unroll
            for (int c = 0; c < 4; c++) acc[a][b][c] = 0.0f;

    const int NIT = NG / 32;   // 64

#pragma unroll
    for (int s = 0; s < 3; s++) {
        unsigned char* st = dsm + s * STG1_B;
        __half* sA = (__half*)st;
        __half* sB = sA + 128 * SLD;
        int k0 = s * 32;
#pragma unroll
        for (int l = 0; l < 2; l++)
            cp_async16(&sA[aRow[l] * SLD + aSeg[l]], &g_Xh[(bm + aRow[l]) * NG + k0 + aSeg[l]]);
        cp_async16(&sB[bRow * SLD + bSeg], &g_B1T[(bn + bRow) * NG + k0 + bSeg]);
        CP_COMMIT();
    }

    for (int it = 0; it < NIT; it++) {
        CP_WAIT(2);
        __syncthreads();
        if (it + 3 < NIT) {
            int s = (it + 3) & 3;
            int k0 = (it + 3) * 32;
            unsigned char* st = dsm + s * STG1_B;
            __half* sA = (__half*)st;
            __half* sB = sA + 128 * SLD;
#pragma unroll
            for (int l = 0; l < 2; l++)
                cp_async16(&sA[aRow[l] * SLD + aSeg[l]], &g_Xh[(bm + aRow[l]) * NG + k0 + aSeg[l]]);
            cp_async16(&sB[bRow * SLD + bSeg], &g_B1T[(bn + bRow) * NG + k0 + bSeg]);
            CP_COMMIT();
        }
        uint32_t stg = sbase + (uint32_t)((it & 3) * STG1_B);
#pragma unroll
        for (int ks = 0; ks < 2; ks++) {
            uint32_t kb = (uint32_t)(ks * 32);
            uint32_t a[4][4], b[2][2];
#pragma unroll
            for (int mi = 0; mi < 4; mi++)
                ldsm_x4(a[mi][0], a[mi][1], a[mi][2], a[mi][3], stg + aoff[mi] + kb);
            ldsm_x4(b[0][0], b[0][1], b[1][0], b[1][1], stg + boff + kb);
#pragma unroll
            for (int mi = 0; mi < 4; mi++)
#pragma unroll
                for (int ni = 0; ni < 2; ni++)
                    MMA_F16(acc[mi][ni], a[mi], b[ni]);
        }
    }
    __syncthreads();

    // Epilogue: stage transposed fp16 cbuf[k][r], then coalesced write C1h[k][r].
    __half* cbuf = (__half*)dsm;   // 64 x SLDE halves = 17408 B
#pragma unroll
    for (int mi = 0; mi < 4; mi++)
#pragma unroll
        for (int ni = 0; ni < 2; ni++) {
            int rl = wm * 64 + mi * 16 + g;
            int cl = wn * 16 + ni * 8 + t2;
            cbuf[cl * SLDE + rl]           = __float2half(acc[mi][ni][0]);
            cbuf[(cl + 1) * SLDE + rl]     = __float2half(acc[mi][ni][1]);
            cbuf[cl * SLDE + rl + 8]       = __float2half(acc[mi][ni][2]);
            cbuf[(cl + 1) * SLDE + rl + 8] = __float2half(acc[mi][ni][3]);
        }
    __syncthreads();
#pragma unroll
    for (int p = 0; p < 8; p++) {
        int idx = tid + p * 256;               // 2048 uint2 = 64k x 32
        int kc = idx >> 5;
        int seg = (idx & 31) * 4;
        *(uint2*)&g_C1h[(bn + kc) * RROWS + bm + seg] = *(uint2*)&cbuf[kc * SLDE + seg];
    }
}

// ---------------------------------------------------------------------------
// Mix (tensor cores): per mode k, C2h[k][b*64+o] = sum_i C1h[k][b*64+i]*W[k][i][o]
//   512 blocks x 128 threads (4 warps); warp = 16 b-rows x 64 o-cols.
// ---------------------------------------------------------------------------
__global__ __launch_bounds__(128) void mix_mma_kernel() {
    int k = blockIdx.x;
    __shared__ __align__(16) __half sA[64][72];
    __shared__ __align__(16) __half sW[64][72];
    const __half* a = &g_C1h[k * RROWS];
    const __half* w = &g_Wt16[k * RROWS];
    int tid = (int)threadIdx.x;
#pragma unroll
    for (int l = 0; l < 4; l++) {
        int idx = tid + l * 128;               // 512 uint4 each
        int r = idx >> 3, seg = (idx & 7) * 8;
        *(uint4*)&sA[r][seg] = *(const uint4*)&a[r * 64 + seg];
        *(uint4*)&sW[r][seg] = *(const uint4*)&w[r * 64 + seg];
    }
    __syncthreads();

    int warp = tid >> 5, lane = tid & 31;
    int g = lane >> 2, t2 = (lane & 3) * 2;
    uint32_t sAb = (uint32_t)__cvta_generic_to_shared(&sA[0][0]);
    uint32_t sWb = (uint32_t)__cvta_generic_to_shared(&sW[0][0]);

    float acc[8][4];
#pragma unroll
    for (int i = 0; i < 8; i++)
#pragma unroll
        for (int j = 0; j < 4; j++) acc[i][j] = 0.0f;

#pragma unroll
    for (int ks = 0; ks < 4; ks++) {
        uint32_t av[4];
        uint32_t aaddr = sAb + ((warp * 16 + (lane & 15)) * 72 + ks * 16 + ((lane >> 4) << 3)) * 2;
        ldsm_x4(av[0], av[1], av[2], av[3], aaddr);
#pragma unroll
        for (int nq = 0; nq < 4; nq++) {
            uint32_t b0, b1, b2, b3;
            uint32_t baddr = sWb + ((ks * 16 + (lane & 15)) * 72 + nq * 16 + ((lane >> 4) << 3)) * 2;
            ldsm_x4_t(b0, b1, b2, b3, baddr);
            uint32_t bb0[2] = {b0, b1}, bb1[2] = {b2, b3};
            MMA_F16(acc[nq * 2], av, bb0);
            MMA_F16(acc[nq * 2 + 1], av, bb1);
        }
    }

    __half* c2 = &g_C2h[k * RROWS];
#pragma unroll
    for (int ni = 0; ni < 8; ni++) {
        int col = ni * 8 + t2;
        __half2 v0 = __floats2half2_rn(acc[ni][0], acc[ni][1]);
        __half2 v1 = __floats2half2_rn(acc[ni][2], acc[ni][3]);
        *(__half2*)&c2[(warp * 16 + g) * 64 + col]     = v0;
        *(__half2*)&c2[(warp * 16 + g + 8) * 64 + col] = v1;
    }
}

// ---------------------------------------------------------------------------
// transpose C2h [k][r] -> C2t [r][k] (fp16)
// ---------------------------------------------------------------------------
__global__ void transpose_C2_kernel() {
    __shared__ __half tile[32][33];
    int k0 = blockIdx.x * 32;
    int r0 = blockIdx.y * 32;
    int tx = threadIdx.x, ty = threadIdx.y;   // (32, 8)
#pragma unroll
    for (int j = 0; j < 32; j += 8)
        tile[ty + j][tx] = g_C2h[(k0 + ty + j) * RROWS + r0 + tx];
    __syncthreads();
#pragma unroll
    for (int j = 0; j < 32; j += 8)
        g_C2t[(r0 + ty + j) * MODES + k0 + tx] = tile[tx][ty + j];
}

// ---------------------------------------------------------------------------
// GEMM3: out[r][n] = sum_k C2t[r][k] * B3[k][n]
//   M=4096, N=2048, K=512. CTA 128x128, 4-stage, 2 CTAs/SM, grid 512.
// ---------------------------------------------------------------------------
__global__ __launch_bounds__(256, 2) void gemm3_mma(float* __restrict__ out) {
    int tid = (int)threadIdx.x;
    int bm = blockIdx.y * 128;   // r
    int bn = blockIdx.x * 128;   // grid n
    int warp = tid >> 5, lane = tid & 31;
    int wm = warp >> 2, wn = warp & 3;
    int g = lane >> 2, t2 = (lane & 3) * 2;

    uint32_t sbase = (uint32_t)__cvta_generic_to_shared(dsm);

    int ldRow[2], ldSeg[2];
#pragma unroll
    for (int l = 0; l < 2; l++) {
        int idx = tid + l * 256;
        ldRow[l] = idx >> 2;
        ldSeg[l] = (idx & 3) * 8;
    }

    uint32_t aoff[4], boff[2];
#pragma unroll
    for (int mi = 0; mi < 4; mi++)
        aoff[mi] = ((wm * 64 + mi * 16 + (lane & 15)) * SLD + ((lane >> 4) << 3)) * 2;
#pragma unroll
    for (int nq = 0; nq < 2; nq++)
        boff[nq] = (uint32_t)(128 * SLD * 2) +
                   ((wn * 32 + nq * 16 + (lane & 7) + ((lane >> 4) << 3)) * SLD +
                    (((lane >> 3) & 1) << 3)) * 2;

    float acc[4][4][4];
#pragma unroll
    for (int a = 0; a < 4; a++)
#pragma unroll
        for (int b = 0; b < 4; b++)
#pragma unroll
            for (int c = 0; c < 4; c++) acc[a][b][c] = 0.0f;

    const int NIT = MODES / 32;  // 16

#pragma unroll
    for (int s = 0; s < 3; s++) {
        unsigned char* st = dsm + s * STG3_B;
        __half* sA = (__half*)st;
        __half* sB = sA + 128 * SLD;
        int k0 = s * 32;
#pragma unroll
        for (int l = 0; l < 2; l++) {
            cp_async16(&sA[ldRow[l] * SLD + ldSeg[l]], &g_C2t[(bm + ldRow[l]) * MODES + k0 + ldSeg[l]]);
            cp_async16(&sB[ldRow[l] * SLD + ldSeg[l]], &g_B3T[(bn + ldRow[l]) * MODES + k0 + ldSeg[l]]);
        }
        CP_COMMIT();
    }

    for (int it = 0; it < NIT; it++) {
        CP_WAIT(2);
        __syncthreads();
        if (it + 3 < NIT) {
            int s = (it + 3) & 3;
            int k0 = (it + 3) * 32;
            unsigned char* st = dsm + s * STG3_B;
            __half* sA = (__half*)st;
            __half* sB = sA + 128 * SLD;
#pragma unroll
            for (int l = 0; l < 2; l++) {
                cp_async16(&sA[ldRow[l] * SLD + ldSeg[l]], &g_C2t[(bm + ldRow[l]) * MODES + k0 + ldSeg[l]]);
                cp_async16(&sB[ldRow[l] * SLD + ldSeg[l]], &g_B3T[(bn + ldRow[l]) * MODES + k0 + ldSeg[l]]);
            }
            CP_COMMIT();
        }
        uint32_t stg = sbase + (uint32_t)((it & 3) * STG3_B);
#pragma unroll
        for (int ks = 0; ks < 2; ks++) {
            uint32_t kb = (uint32_t)(ks * 32);
            uint32_t a[4][4], b[4][2];
#pragma unroll
            for (int mi = 0; mi < 4; mi++)
                ldsm_x4(a[mi][0], a[mi][1], a[mi][2], a[mi][3], stg + aoff[mi] + kb);
#pragma unroll
            for (int nq = 0; nq < 2; nq++)
                ldsm_x4(b[nq * 2][0], b[nq * 2][1], b[nq * 2 + 1][0], b[nq * 2 + 1][1],
                        stg + boff[nq] + kb);
#pragma unroll
            for (int mi = 0; mi < 4; mi++)
#pragma unroll
                for (int ni = 0; ni < 4; ni++)
                    MMA_F16(acc[mi][ni], a[mi], b[ni]);
        }
    }

#pragma unroll
    for (int mi = 0; mi < 4; mi++)
#pragma unroll
        for (int ni = 0; ni < 4; ni++) {
            int row = bm + wm * 64 + mi * 16 + g;
            int col = bn + wn * 32 + ni * 8 + t2;
            float2 v0 = make_float2(acc[mi][ni][0], acc[mi][ni][1]);
            float2 v1 = make_float2(acc[mi][ni][2], acc[mi][ni][3]);
            *(float2*)&out[row * NG + col] = v0;
            *(float2*)&out[(row + 8) * NG + col] = v1;
        }
}

// ---------------------------------------------------------------------------
// Launch
// ---------------------------------------------------------------------------
extern "C" void kernel_launch(void* const* d_in, const int* in_sizes, int n_in,
                              void* d_out, int out_size) {
    const float* x = (const float*)d_in[0];   // [64, 64, 2048] f32
    const float* w = (const float*)d_in[1];   // [64, 64, 512]  f32
    float* out = (float*)d_out;               // [64, 64, 2048] f32

    cudaFuncSetAttribute(gemm1_mma, cudaFuncAttributeMaxDynamicSharedMemorySize, NSTG * STG1_B);
    cudaFuncSetAttribute(gemm3_mma, cudaFuncAttributeMaxDynamicSharedMemorySize, NSTG * STG3_B);

    init_table_kernel<<<16, 256>>>();
    init_M_kernel<<<(MODES * NG + 255) / 256, 256>>>();
    convert_X_kernel<<<(RROWS * NG / 4 + 255) / 256, 256>>>(x);
    transpose_W_kernel<<<dim3(MODES / 32, RROWS / 32), dim3(32, 8)>>>(w);
    gemm1_mma<<<dim3(MODES / 64, RROWS / 128), 256, NSTG * STG1_B>>>();
    mix_mma_kernel<<<MODES, 128>>>();
    transpose_C2_kernel<<<dim3(MODES / 32, RROWS / 32), dim3(32, 8)>>>();
    gemm3_mma<<<dim3(NG / 128, RROWS / 128), 256, NSTG * STG3_B>>>(out);
}

// round 6
// speedup vs baseline: 5.6059x; 1.2977x over previous
#include <cuda_runtime.h>
#include <cuda_fp16.h>
#include <stdint.h>

#define NG      2048
#define NH      1024          // folded grid length
#define MODES   512
#define MH      256           // modes per parity
#define RROWS   4096
#define SLD     40            // padded smem row stride (half); conflict-free ldmatrix
#define SLDE    136           // epilogue cbuf stride (half)
#define STG_B   ((128 + 64) * SLD * 2)   // stage bytes: 15360
#define NSTG    4

// ---------------------------------------------------------------------------
// Static device scratch
// ---------------------------------------------------------------------------
__device__ float g_cosTab[2 * (NG - 1)];
__device__ __align__(16) __half g_B1e[MH * NH];        // [k2][n]  even fwd op, c[n] folded
__device__ __align__(16) __half g_B1o[MH * NH];        // [k2][n]  odd  fwd op
__device__ __align__(16) __half g_B3e[NH * MH];        // [n][k2]  even inv op, c[k] folded
__device__ __align__(16) __half g_B3o[NH * MH];        // [n][k2]  odd  inv op
__device__ __align__(16) __half g_Xe[RROWS * NH];      // [r][n]  x[n]+x[2047-n]
__device__ __align__(16) __half g_Xd[RROWS * NH];      // [r][n]  x[n]-x[2047-n]
__device__ __align__(16) __half g_C1h[MODES * RROWS];  // [pk][r] parity-major modes
__device__ __align__(16) __half g_Wt16[MODES * RROWS]; // [pk][i*64+o] parity-major
__device__ __align__(16) __half g_C2h[MODES * RROWS];  // [pk][r]
__device__ __align__(16) __half g_C2t[RROWS * MODES];  // [r][pk]

// ---------------------------------------------------------------------------
// Async-copy / MMA / ldmatrix helpers
// ---------------------------------------------------------------------------
__device__ __forceinline__ void cp_async16(void* smem, const void* gmem) {
    uint32_t s = (uint32_t)__cvta_generic_to_shared(smem);
    asm volatile("cp.async.cg.shared.global [%0], [%1], 16;\n" :: "r"(s), "l"(gmem));
}
#define CP_COMMIT() asm volatile("cp.async.commit_group;\n" ::: "memory")
#define CP_WAIT(n)  asm volatile("cp.async.wait_group %0;\n" :: "n"(n) : "memory")

#define MMA_F16(c, a, b)                                                        \
    asm volatile(                                                               \
        "mma.sync.aligned.m16n8k16.row.col.f32.f16.f16.f32 "                    \
        "{%0,%1,%2,%3},{%4,%5,%6,%7},{%8,%9},{%0,%1,%2,%3};\n"                  \
        : "+f"((c)[0]), "+f"((c)[1]), "+f"((c)[2]), "+f"((c)[3])                \
        : "r"((a)[0]), "r"((a)[1]), "r"((a)[2]), "r"((a)[3]),                   \
          "r"((b)[0]), "r"((b)[1]))

__device__ __forceinline__ void ldsm_x4(uint32_t& r0, uint32_t& r1, uint32_t& r2,
                                        uint32_t& r3, uint32_t saddr) {
    asm volatile("ldmatrix.sync.aligned.m8n8.x4.shared.b16 {%0,%1,%2,%3}, [%4];"
                 : "=r"(r0), "=r"(r1), "=r"(r2), "=r"(r3) : "r"(saddr));
}
__device__ __forceinline__ void ldsm_x4_t(uint32_t& r0, uint32_t& r1, uint32_t& r2,
                                          uint32_t& r3, uint32_t saddr) {
    asm volatile("ldmatrix.sync.aligned.m8n8.x4.trans.shared.b16 {%0,%1,%2,%3}, [%4];"
                 : "=r"(r0), "=r"(r1), "=r"(r2), "=r"(r3) : "r"(saddr));
}

// ---------------------------------------------------------------------------
// Init kernels
// ---------------------------------------------------------------------------
__global__ void init_table_kernel() {
    int i = blockIdx.x * blockDim.x + threadIdx.x;
    if (i < 2 * (NG - 1))
        g_cosTab[i] = cospif((float)i * (1.0f / (float)(NG - 1)));
}

// Build folded operators. idx over [MH x NH].
__global__ void init_M_kernel() {
    int idx = blockIdx.x * blockDim.x + threadIdx.x;
    if (idx >= MH * NH) return;
    int k2 = idx >> 10, n = idx & (NH - 1);
    int ke = 2 * k2, ko = 2 * k2 + 1;
    float ve = g_cosTab[(ke * n) % (2 * (NG - 1))];
    float vo = g_cosTab[(ko * n) % (2 * (NG - 1))];
    float cn = (n == 0) ? 1.0f : 2.0f;           // c[n]; pair partner has same weight
    g_B1e[idx] = __float2half(ve * cn);
    g_B1o[idx] = __float2half(vo * cn);
    float cke = (ke == 0) ? 1.0f : 2.0f;
    g_B3e[n * MH + k2] = __float2half(ve * cke);
    g_B3o[n * MH + k2] = __float2half(vo * 2.0f);
}

// e/d fold of X: e[r][n]=x[r][n]+x[r][2047-n], d=x-x  (n<1024), fp16
__global__ void convert_X_kernel(const float* __restrict__ x) {
    int idx = blockIdx.x * blockDim.x + threadIdx.x;   // 4096*256 threads
    if (idx >= RROWS * (NH / 4)) return;
    int r = idx >> 8;
    int n0 = (idx & 255) * 4;
    float4 fa = *(const float4*)&x[r * NG + n0];
    float4 fb = *(const float4*)&x[r * NG + (NG - 4 - n0)];   // covers 2047-n0-3 .. 2047-n0
    float a[4] = {fa.x, fa.y, fa.z, fa.w};
    float b[4] = {fb.w, fb.z, fb.y, fb.x};                    // b[i] = x[2047-(n0+i)]
    union { __half h[4]; uint2 u; } pe, pd;
#pragma unroll
    for (int i = 0; i < 4; i++) {
        pe.h[i] = __float2half(a[i] + b[i]);
        pd.h[i] = __float2half(a[i] - b[i]);
    }
    *(uint2*)&g_Xe[r * NH + n0] = pe.u;
    *(uint2*)&g_Xd[r * NH + n0] = pd.u;
}

// transpose weights [i,o,k] f32 -> Wt16[pk][i*64+o] fp16, pk = (k&1)*256 + (k>>1)
__global__ void transpose_W_kernel(const float* __restrict__ w) {
    __shared__ float tile[32][33];
    int kBase = blockIdx.x * 32;
    int rBase = blockIdx.y * 32;
    int tx = threadIdx.x, ty = threadIdx.y;   // (32, 8)
#pragma unroll
    for (int j = 0; j < 32; j += 8)
        tile[ty + j][tx] = w[(rBase + ty + j) * MODES + kBase + tx];
    __syncthreads();
#pragma unroll
    for (int j = 0; j < 32; j += 8) {
        int k = kBase + ty + j;
        int pk = (k & 1) * MH + (k >> 1);
        g_Wt16[pk * RROWS + rBase + tx] = __float2half(tile[tx][ty + j]);
    }
}

// ---------------------------------------------------------------------------
// GEMM1 (folded): C1h[p*256+bn+kc][r] = sum_{n<1024} A_p[r][n] * B_p[k][n]
//   A0=Xe/B1e (even modes), A1=Xd/B1o (odd). M=4096, N=256, K=1024.
//   CTA 128m x 64n, BK=32, 4-stage cp.async, grid (4,32,2).
// ---------------------------------------------------------------------------
extern __shared__ __align__(16) unsigned char dsm[];

__global__ __launch_bounds__(256, 2) void gemm1_mma() {
    int tid = (int)threadIdx.x;
    int bm = blockIdx.y * 128;   // r
    int bn = blockIdx.x * 64;    // k2 within parity
    int p  = blockIdx.z;
    const __half* Asrc = p ? g_Xd : g_Xe;
    const __half* Bsrc = p ? g_B1o : g_B1e;

    int warp = tid >> 5, lane = tid & 31;
    int wm = warp >> 2, wn = warp & 3;
    int g = lane >> 2, t2 = (lane & 3) * 2;

    uint32_t sbase = (uint32_t)__cvta_generic_to_shared(dsm);

    int aRow[2], aSeg[2];
#pragma unroll
    for (int l = 0; l < 2; l++) {
        int idx = tid + l * 256;
        aRow[l] = idx >> 2;
        aSeg[l] = (idx & 3) * 8;
    }
    int bRow = tid >> 2, bSeg = (tid & 3) * 8;

    uint32_t aoff[4];
#pragma unroll
    for (int mi = 0; mi < 4; mi++)
        aoff[mi] = ((wm * 64 + mi * 16 + (lane & 15)) * SLD + ((lane >> 4) << 3)) * 2;
    uint32_t boff = (uint32_t)(128 * SLD * 2) +
                    ((wn * 16 + (lane & 7) + ((lane >> 4) << 3)) * SLD +
                     (((lane >> 3) & 1) << 3)) * 2;

    float acc[4][2][4];
#pragma unroll
    for (int a = 0; a < 4; a++)
#pragma unroll
        for (int b = 0; b < 2; b++)
#pragma unroll
            for (int c = 0; c < 4; c++) acc[a][b][c] = 0.0f;

    const int NIT = NH / 32;   // 32

#pragma unroll
    for (int s = 0; s < 3; s++) {
        __half* sA = (__half*)(dsm + s * STG_B);
        __half* sB = sA + 128 * SLD;
        int k0 = s * 32;
#pragma unroll
        for (int l = 0; l < 2; l++)
            cp_async16(&sA[aRow[l] * SLD + aSeg[l]], &Asrc[(bm + aRow[l]) * NH + k0 + aSeg[l]]);
        cp_async16(&sB[bRow * SLD + bSeg], &Bsrc[(bn + bRow) * NH + k0 + bSeg]);
        CP_COMMIT();
    }

    for (int it = 0; it < NIT; it++) {
        CP_WAIT(2);
        __syncthreads();
        if (it + 3 < NIT) {
            int s = (it + 3) & 3;
            int k0 = (it + 3) * 32;
            __half* sA = (__half*)(dsm + s * STG_B);
            __half* sB = sA + 128 * SLD;
#pragma unroll
            for (int l = 0; l < 2; l++)
                cp_async16(&sA[aRow[l] * SLD + aSeg[l]], &Asrc[(bm + aRow[l]) * NH + k0 + aSeg[l]]);
            cp_async16(&sB[bRow * SLD + bSeg], &Bsrc[(bn + bRow) * NH + k0 + bSeg]);
            CP_COMMIT();
        }
        uint32_t stg = sbase + (uint32_t)((it & 3) * STG_B);
#pragma unroll
        for (int ks = 0; ks < 2; ks++) {
            uint32_t kb = (uint32_t)(ks * 32);
            uint32_t a[4][4], b[2][2];
#pragma unroll
            for (int mi = 0; mi < 4; mi++)
                ldsm_x4(a[mi][0], a[mi][1], a[mi][2], a[mi][3], stg + aoff[mi] + kb);
            ldsm_x4(b[0][0], b[0][1], b[1][0], b[1][1], stg + boff + kb);
#pragma unroll
            for (int mi = 0; mi < 4; mi++)
#pragma unroll
                for (int ni = 0; ni < 2; ni++)
                    MMA_F16(acc[mi][ni], a[mi], b[ni]);
        }
    }
    __syncthreads();

    // Epilogue: stage transposed fp16 cbuf[k][r], coalesced write C1h (parity-major).
    __half* cbuf = (__half*)dsm;   // 64 x SLDE halves = 17408 B
#pragma unroll
    for (int mi = 0; mi < 4; mi++)
#pragma unroll
        for (int ni = 0; ni < 2; ni++) {
            int rl = wm * 64 + mi * 16 + g;
            int cl = wn * 16 + ni * 8 + t2;
            cbuf[cl * SLDE + rl]           = __float2half(acc[mi][ni][0]);
            cbuf[(cl + 1) * SLDE + rl]     = __float2half(acc[mi][ni][1]);
            cbuf[cl * SLDE + rl + 8]       = __float2half(acc[mi][ni][2]);
            cbuf[(cl + 1) * SLDE + rl + 8] = __float2half(acc[mi][ni][3]);
        }
    __syncthreads();
    int kgBase = p * MH + bn;
#pragma unroll
    for (int q = 0; q < 8; q++) {
        int idx = tid + q * 256;               // 2048 uint2 = 64k x 32
        int kc = idx >> 5;
        int seg = (idx & 31) * 4;
        *(uint2*)&g_C1h[(kgBase + kc) * RROWS + bm + seg] = *(uint2*)&cbuf[kc * SLDE + seg];
    }
}

// ---------------------------------------------------------------------------
// Mix (tensor cores): per pk, C2h[pk][b*64+o] = sum_i C1h[pk][b*64+i]*Wt16[pk][i][o]
// ---------------------------------------------------------------------------
__global__ __launch_bounds__(128) void mix_mma_kernel() {
    int k = blockIdx.x;
    __shared__ __align__(16) __half sA[64][72];
    __shared__ __align__(16) __half sW[64][72];
    const __half* a = &g_C1h[k * RROWS];
    const __half* w = &g_Wt16[k * RROWS];
    int tid = (int)threadIdx.x;
#pragma unroll
    for (int l = 0; l < 4; l++) {
        int idx = tid + l * 128;
        int r = idx >> 3, seg = (idx & 7) * 8;
        *(uint4*)&sA[r][seg] = *(const uint4*)&a[r * 64 + seg];
        *(uint4*)&sW[r][seg] = *(const uint4*)&w[r * 64 + seg];
    }
    __syncthreads();

    int warp = tid >> 5, lane = tid & 31;
    int g = lane >> 2, t2 = (lane & 3) * 2;
    uint32_t sAb = (uint32_t)__cvta_generic_to_shared(&sA[0][0]);
    uint32_t sWb = (uint32_t)__cvta_generic_to_shared(&sW[0][0]);

    float acc[8][4];
#pragma unroll
    for (int i = 0; i < 8; i++)
#pragma unroll
        for (int j = 0; j < 4; j++) acc[i][j] = 0.0f;

#pragma unroll
    for (int ks = 0; ks < 4; ks++) {
        uint32_t av[4];
        uint32_t aaddr = sAb + ((warp * 16 + (lane & 15)) * 72 + ks * 16 + ((lane >> 4) << 3)) * 2;
        ldsm_x4(av[0], av[1], av[2], av[3], aaddr);
#pragma unroll
        for (int nq = 0; nq < 4; nq++) {
            uint32_t b0, b1, b2, b3;
            uint32_t baddr = sWb + ((ks * 16 + (lane & 15)) * 72 + nq * 16 + ((lane >> 4) << 3)) * 2;
            ldsm_x4_t(b0, b1, b2, b3, baddr);
            uint32_t bb0[2] = {b0, b1}, bb1[2] = {b2, b3};
            MMA_F16(acc[nq * 2], av, bb0);
            MMA_F16(acc[nq * 2 + 1], av, bb1);
        }
    }

    __half* c2 = &g_C2h[k * RROWS];
#pragma unroll
    for (int ni = 0; ni < 8; ni++) {
        int col = ni * 8 + t2;
        __half2 v0 = __floats2half2_rn(acc[ni][0], acc[ni][1]);
        __half2 v1 = __floats2half2_rn(acc[ni][2], acc[ni][3]);
        *(__half2*)&c2[(warp * 16 + g) * 64 + col]     = v0;
        *(__half2*)&c2[(warp * 16 + g + 8) * 64 + col] = v1;
    }
}

// ---------------------------------------------------------------------------
// transpose C2h [pk][r] -> C2t [r][pk] (fp16)
// ---------------------------------------------------------------------------
__global__ void transpose_C2_kernel() {
    __shared__ __half tile[32][33];
    int k0 = blockIdx.x * 32;
    int r0 = blockIdx.y * 32;
    int tx = threadIdx.x, ty = threadIdx.y;   // (32, 8)
#pragma unroll
    for (int j = 0; j < 32; j += 8)
        tile[ty + j][tx] = g_C2h[(k0 + ty + j) * RROWS + r0 + tx];
    __syncthreads();
#pragma unroll
    for (int j = 0; j < 32; j += 8)
        g_C2t[(r0 + ty + j) * MODES + k0 + tx] = tile[tx][ty + j];
}

// ---------------------------------------------------------------------------
// GEMM3 (folded + butterfly): Se[r][n] = sum_{k2} C2t[r][k2]     * B3e[n][k2]
//                             So[r][n] = sum_{k2} C2t[r][256+k2] * B3o[n][k2]
//   out[r][n] = Se+So; out[r][2047-n] = Se-So   (n < 1024)
//   M=4096, N=1024, Kphase=256x2. CTA 128x64, 4-stage pipeline spanning phases.
// ---------------------------------------------------------------------------
__global__ __launch_bounds__(256, 2) void gemm3_mma(float* __restrict__ out) {
    int tid = (int)threadIdx.x;
    int bm = blockIdx.y * 128;   // r
    int bn = blockIdx.x * 64;    // n (folded half)
    int warp = tid >> 5, lane = tid & 31;
    int wm = warp >> 2, wn = warp & 3;
    int g = lane >> 2, t2 = (lane & 3) * 2;

    uint32_t sbase = (uint32_t)__cvta_generic_to_shared(dsm);

    int aRow[2], aSeg[2];
#pragma unroll
    for (int l = 0; l < 2; l++) {
        int idx = tid + l * 256;
        aRow[l] = idx >> 2;
        aSeg[l] = (idx & 3) * 8;
    }
    int bRow = tid >> 2, bSeg = (tid & 3) * 8;

    uint32_t aoff[4];
#pragma unroll
    for (int mi = 0; mi < 4; mi++)
        aoff[mi] = ((wm * 64 + mi * 16 + (lane & 15)) * SLD + ((lane >> 4) << 3)) * 2;
    uint32_t boff = (uint32_t)(128 * SLD * 2) +
                    ((wn * 16 + (lane & 7) + ((lane >> 4) << 3)) * SLD +
                     (((lane >> 3) & 1) << 3)) * 2;

    float acc_e[4][2][4], acc_o[4][2][4];
#pragma unroll
    for (int a = 0; a < 4; a++)
#pragma unroll
        for (int b = 0; b < 2; b++)
#pragma unroll
            for (int c = 0; c < 4; c++) { acc_e[a][b][c] = 0.0f; acc_o[a][b][c] = 0.0f; }

    // global iteration j in [0,16): phase = j>>3, kk = (j&7)*32
#define G3_LOAD(j)                                                                   \
    do {                                                                             \
        int s_ = (j) & 3;                                                            \
        int ph_ = (j) >> 3;                                                          \
        int kk_ = ((j) & 7) * 32;                                                    \
        __half* sA_ = (__half*)(dsm + s_ * STG_B);                                   \
        __half* sB_ = sA_ + 128 * SLD;                                               \
        const __half* Bs_ = ph_ ? g_B3o : g_B3e;                                     \
        _Pragma("unroll")                                                            \
        for (int l_ = 0; l_ < 2; l_++)                                               \
            cp_async16(&sA_[aRow[l_] * SLD + aSeg[l_]],                              \
                       &g_C2t[(bm + aRow[l_]) * MODES + ph_ * MH + kk_ + aSeg[l_]]); \
        cp_async16(&sB_[bRow * SLD + bSeg], &Bs_[(bn + bRow) * MH + kk_ + bSeg]);    \
        CP_COMMIT();                                                                 \
    } while (0)

#define G3_COMPUTE(j, ACC)                                                           \
    do {                                                                             \
        uint32_t stg_ = sbase + (uint32_t)(((j) & 3) * STG_B);                       \
        _Pragma("unroll")                                                            \
        for (int ks_ = 0; ks_ < 2; ks_++) {                                          \
            uint32_t kb_ = (uint32_t)(ks_ * 32);                                     \
            uint32_t a_[4][4], b_[2][2];                                             \
            _Pragma("unroll")                                                        \
            for (int mi_ = 0; mi_ < 4; mi_++)                                        \
                ldsm_x4(a_[mi_][0], a_[mi_][1], a_[mi_][2], a_[mi_][3],              \
                        stg_ + aoff[mi_] + kb_);                                     \
            ldsm_x4(b_[0][0], b_[0][1], b_[1][0], b_[1][1], stg_ + boff + kb_);      \
            _Pragma("unroll")                                                        \
            for (int mi_ = 0; mi_ < 4; mi_++)                                        \
                _Pragma("unroll")                                                    \
                for (int ni_ = 0; ni_ < 2; ni_++)                                    \
                    MMA_F16(ACC[mi_][ni_], a_[mi_], b_[ni_]);                        \
        }                                                                            \
    } while (0)

#pragma unroll
    for (int s = 0; s < 3; s++) G3_LOAD(s);

    for (int j = 0; j < 8; j++) {
        CP_WAIT(2);
        __syncthreads();
        G3_LOAD(j + 3);
        G3_COMPUTE(j, acc_e);
        __syncthreads();
    }
    for (int j = 8; j < 16; j++) {
        CP_WAIT(2);
        __syncthreads();
        if (j + 3 < 16) G3_LOAD(j + 3);
        G3_COMPUTE(j, acc_o);
        __syncthreads();
    }

    // Butterfly epilogue: out[r][n] = e+o, out[r][2047-n] = e-o
#pragma unroll
    for (int mi = 0; mi < 4; mi++)
#pragma unroll
        for (int ni = 0; ni < 2; ni++) {
            int row = bm + wm * 64 + mi * 16 + g;
            int col = bn + wn * 16 + ni * 8 + t2;
            float e0 = acc_e[mi][ni][0], e1 = acc_e[mi][ni][1];
            float e2 = acc_e[mi][ni][2], e3 = acc_e[mi][ni][3];
            float o0 = acc_o[mi][ni][0], o1 = acc_o[mi][ni][1];
            float o2 = acc_o[mi][ni][2], o3 = acc_o[mi][ni][3];
            *(float2*)&out[row * NG + col]       = make_float2(e0 + o0, e1 + o1);
            *(float2*)&out[(row + 8) * NG + col] = make_float2(e2 + o2, e3 + o3);
            int mcol = NG - 2 - col;   // float2 covering {2047-(col+1), 2047-col}
            *(float2*)&out[row * NG + mcol]       = make_float2(e1 - o1, e0 - o0);
            *(float2*)&out[(row + 8) * NG + mcol] = make_float2(e3 - o3, e2 - o2);
        }
}

// ---------------------------------------------------------------------------
// Launch
// ---------------------------------------------------------------------------
extern "C" void kernel_launch(void* const* d_in, const int* in_sizes, int n_in,
                              void* d_out, int out_size) {
    const float* x = (const float*)d_in[0];   // [64, 64, 2048] f32
    const float* w = (const float*)d_in[1];   // [64, 64, 512]  f32
    float* out = (float*)d_out;               // [64, 64, 2048] f32

    cudaFuncSetAttribute(gemm1_mma, cudaFuncAttributeMaxDynamicSharedMemorySize, NSTG * STG_B);
    cudaFuncSetAttribute(gemm3_mma, cudaFuncAttributeMaxDynamicSharedMemorySize, NSTG * STG_B);

    init_table_kernel<<<16, 256>>>();
    init_M_kernel<<<(MH * NH + 255) / 256, 256>>>();
    convert_X_kernel<<<(RROWS * (NH / 4) + 255) / 256, 256>>>(x);
    transpose_W_kernel<<<dim3(MODES / 32, RROWS / 32), dim3(32, 8)>>>(w);
    gemm1_mma<<<dim3(MH / 64, RROWS / 128, 2), 256, NSTG * STG_B>>>();
    mix_mma_kernel<<<MODES, 128>>>();
    transpose_C2_kernel<<<dim3(MODES / 32, RROWS / 32), dim3(32, 8)>>>();
    gemm3_mma<<<dim3(NH / 64, RROWS / 128), 256, NSTG * STG_B>>>(out);
}

// round 7
// speedup vs baseline: 6.0560x; 1.0803x over previous
#include <cuda_runtime.h>
#include <cuda_fp16.h>
#include <stdint.h>

#define NG      2048
#define NH      1024          // folded grid length
#define MODES   512
#define MH      256           // modes per parity
#define RROWS   4096
#define SLD     40            // padded smem row stride (half); conflict-free ldmatrix
#define SLDA    136           // gemm3 A-tile row stride (half), [k][r] layout
#define SLDE    136           // epilogue cbuf stride (half)
#define STG_B   ((128 + 64) * SLD * 2)            // gemm1 stage bytes: 15360
#define STG3_B  (32 * SLDA * 2 + 64 * SLD * 2)    // gemm3 stage bytes: 13824
#define NSTG    4

// ---------------------------------------------------------------------------
// Static device scratch
// ---------------------------------------------------------------------------
__device__ float g_cosTab[2 * (NG - 1)];
__device__ __align__(16) __half g_B1e[MH * NH];        // [k2][n]  even fwd op, c[n] folded
__device__ __align__(16) __half g_B1o[MH * NH];        // [k2][n]  odd  fwd op
__device__ __align__(16) __half g_B3e[NH * MH];        // [n][k2]  even inv op, c[k] folded
__device__ __align__(16) __half g_B3o[NH * MH];        // [n][k2]  odd  inv op
__device__ __align__(16) __half g_Xe[RROWS * NH];      // [r][n]  x[n]+x[2047-n]
__device__ __align__(16) __half g_Xd[RROWS * NH];      // [r][n]  x[n]-x[2047-n]
__device__ __align__(16) __half g_C1h[MODES * RROWS];  // [pk][r] parity-major modes
__device__ __align__(16) __half g_Wt16[MODES * RROWS]; // [pk][i*64+o] parity-major
__device__ __align__(16) __half g_C2h[MODES * RROWS];  // [pk][r]

// ---------------------------------------------------------------------------
// Async-copy / MMA / ldmatrix helpers
// ---------------------------------------------------------------------------
__device__ __forceinline__ void cp_async16(void* smem, const void* gmem) {
    uint32_t s = (uint32_t)__cvta_generic_to_shared(smem);
    asm volatile("cp.async.cg.shared.global [%0], [%1], 16;\n" :: "r"(s), "l"(gmem));
}
#define CP_COMMIT() asm volatile("cp.async.commit_group;\n" ::: "memory")
#define CP_WAIT(n)  asm volatile("cp.async.wait_group %0;\n" :: "n"(n) : "memory")

#define MMA_F16(c, a, b)                                                        \
    asm volatile(                                                               \
        "mma.sync.aligned.m16n8k16.row.col.f32.f16.f16.f32 "                    \
        "{%0,%1,%2,%3},{%4,%5,%6,%7},{%8,%9},{%0,%1,%2,%3};\n"                  \
        : "+f"((c)[0]), "+f"((c)[1]), "+f"((c)[2]), "+f"((c)[3])                \
        : "r"((a)[0]), "r"((a)[1]), "r"((a)[2]), "r"((a)[3]),                   \
          "r"((b)[0]), "r"((b)[1]))

__device__ __forceinline__ void ldsm_x4(uint32_t& r0, uint32_t& r1, uint32_t& r2,
                                        uint32_t& r3, uint32_t saddr) {
    asm volatile("ldmatrix.sync.aligned.m8n8.x4.shared.b16 {%0,%1,%2,%3}, [%4];"
                 : "=r"(r0), "=r"(r1), "=r"(r2), "=r"(r3) : "r"(saddr));
}
__device__ __forceinline__ void ldsm_x4_t(uint32_t& r0, uint32_t& r1, uint32_t& r2,
                                          uint32_t& r3, uint32_t saddr) {
    asm volatile("ldmatrix.sync.aligned.m8n8.x4.trans.shared.b16 {%0,%1,%2,%3}, [%4];"
                 : "=r"(r0), "=r"(r1), "=r"(r2), "=r"(r3) : "r"(saddr));
}

// ---------------------------------------------------------------------------
// Init kernels
// ---------------------------------------------------------------------------
__global__ void init_table_kernel() {
    int i = blockIdx.x * blockDim.x + threadIdx.x;
    if (i < 2 * (NG - 1))
        g_cosTab[i] = cospif((float)i * (1.0f / (float)(NG - 1)));
}

__global__ void init_M_kernel() {
    int idx = blockIdx.x * blockDim.x + threadIdx.x;
    if (idx >= MH * NH) return;
    int k2 = idx >> 10, n = idx & (NH - 1);
    int ke = 2 * k2, ko = 2 * k2 + 1;
    float ve = g_cosTab[(ke * n) % (2 * (NG - 1))];
    float vo = g_cosTab[(ko * n) % (2 * (NG - 1))];
    float cn = (n == 0) ? 1.0f : 2.0f;
    g_B1e[idx] = __float2half(ve * cn);
    g_B1o[idx] = __float2half(vo * cn);
    float cke = (ke == 0) ? 1.0f : 2.0f;
    g_B3e[n * MH + k2] = __float2half(ve * cke);
    g_B3o[n * MH + k2] = __float2half(vo * 2.0f);
}

// e/d fold of X: e[r][n]=x[r][n]+x[r][2047-n], d=x-x  (n<1024), fp16
__global__ void convert_X_kernel(const float* __restrict__ x) {
    int idx = blockIdx.x * blockDim.x + threadIdx.x;
    if (idx >= RROWS * (NH / 4)) return;
    int r = idx >> 8;
    int n0 = (idx & 255) * 4;
    float4 fa = *(const float4*)&x[r * NG + n0];
    float4 fb = *(const float4*)&x[r * NG + (NG - 4 - n0)];
    float a[4] = {fa.x, fa.y, fa.z, fa.w};
    float b[4] = {fb.w, fb.z, fb.y, fb.x};
    union { __half h[4]; uint2 u; } pe, pd;
#pragma unroll
    for (int i = 0; i < 4; i++) {
        pe.h[i] = __float2half(a[i] + b[i]);
        pd.h[i] = __float2half(a[i] - b[i]);
    }
    *(uint2*)&g_Xe[r * NH + n0] = pe.u;
    *(uint2*)&g_Xd[r * NH + n0] = pd.u;
}

// transpose weights [i,o,k] f32 -> Wt16[pk][i*64+o] fp16, pk = (k&1)*256 + (k>>1)
// 64k x 32r tiles, [k][r] smem staging, vectorized both sides.
__global__ __launch_bounds__(256) void transpose_W_kernel(const float* __restrict__ w) {
    __shared__ float tile[64][33];   // [k][r], stride 33 words
    int kBase = blockIdx.x * 64;
    int rBase = blockIdx.y * 32;
    int tid = (int)threadIdx.x;
#pragma unroll
    for (int l = 0; l < 2; l++) {
        int idx = tid + l * 256;
        int r = idx >> 4;          // 0..31
        int q = idx & 15;          // k-group of 4
        float4 v = *(const float4*)&w[(rBase + r) * MODES + kBase + q * 4];
        tile[q * 4 + 0][r] = v.x;
        tile[q * 4 + 1][r] = v.y;
        tile[q * 4 + 2][r] = v.z;
        tile[q * 4 + 3][r] = v.w;
    }
    __syncthreads();
    {
        int kk = tid >> 2;          // 0..63
        int seg = (tid & 3) * 8;    // 0,8,16,24
        int k = kBase + kk;
        int pk = (k & 1) * MH + (k >> 1);
        union { __half h[8]; uint4 u; } pkt;
#pragma unroll
        for (int c = 0; c < 8; c++) pkt.h[c] = __float2half(tile[kk][seg + c]);
        *(uint4*)&g_Wt16[pk * RROWS + rBase + seg] = pkt.u;
    }
}

// ---------------------------------------------------------------------------
// GEMM1 (folded): C1h[p*256+bn+kc][r] = sum_{n<1024} A_p[r][n] * B_p[k][n]
// ---------------------------------------------------------------------------
extern __shared__ __align__(16) unsigned char dsm[];

__global__ __launch_bounds__(256, 2) void gemm1_mma() {
    int tid = (int)threadIdx.x;
    int bm = blockIdx.y * 128;   // r
    int bn = blockIdx.x * 64;    // k2 within parity
    int p  = blockIdx.z;
    const __half* Asrc = p ? g_Xd : g_Xe;
    const __half* Bsrc = p ? g_B1o : g_B1e;

    int warp = tid >> 5, lane = tid & 31;
    int wm = warp >> 2, wn = warp & 3;
    int g = lane >> 2, t2 = (lane & 3) * 2;

    uint32_t sbase = (uint32_t)__cvta_generic_to_shared(dsm);

    int aRow[2], aSeg[2];
#pragma unroll
    for (int l = 0; l < 2; l++) {
        int idx = tid + l * 256;
        aRow[l] = idx >> 2;
        aSeg[l] = (idx & 3) * 8;
    }
    int bRow = tid >> 2, bSeg = (tid & 3) * 8;

    uint32_t aoff[4];
#pragma unroll
    for (int mi = 0; mi < 4; mi++)
        aoff[mi] = ((wm * 64 + mi * 16 + (lane & 15)) * SLD + ((lane >> 4) << 3)) * 2;
    uint32_t boff = (uint32_t)(128 * SLD * 2) +
                    ((wn * 16 + (lane & 7) + ((lane >> 4) << 3)) * SLD +
                     (((lane >> 3) & 1) << 3)) * 2;

    float acc[4][2][4];
#pragma unroll
    for (int a = 0; a < 4; a++)
#pragma unroll
        for (int b = 0; b < 2; b++)
#pragma unroll
            for (int c = 0; c < 4; c++) acc[a][b][c] = 0.0f;

    const int NIT = NH / 32;   // 32

#pragma unroll
    for (int s = 0; s < 3; s++) {
        __half* sA = (__half*)(dsm + s * STG_B);
        __half* sB = sA + 128 * SLD;
        int k0 = s * 32;
#pragma unroll
        for (int l = 0; l < 2; l++)
            cp_async16(&sA[aRow[l] * SLD + aSeg[l]], &Asrc[(bm + aRow[l]) * NH + k0 + aSeg[l]]);
        cp_async16(&sB[bRow * SLD + bSeg], &Bsrc[(bn + bRow) * NH + k0 + bSeg]);
        CP_COMMIT();
    }

    for (int it = 0; it < NIT; it++) {
        CP_WAIT(2);
        __syncthreads();
        if (it + 3 < NIT) {
            int s = (it + 3) & 3;
            int k0 = (it + 3) * 32;
            __half* sA = (__half*)(dsm + s * STG_B);
            __half* sB = sA + 128 * SLD;
#pragma unroll
            for (int l = 0; l < 2; l++)
                cp_async16(&sA[aRow[l] * SLD + aSeg[l]], &Asrc[(bm + aRow[l]) * NH + k0 + aSeg[l]]);
            cp_async16(&sB[bRow * SLD + bSeg], &Bsrc[(bn + bRow) * NH + k0 + bSeg]);
            CP_COMMIT();
        }
        uint32_t stg = sbase + (uint32_t)((it & 3) * STG_B);
#pragma unroll
        for (int ks = 0; ks < 2; ks++) {
            uint32_t kb = (uint32_t)(ks * 32);
            uint32_t a[4][4], b[2][2];
#pragma unroll
            for (int mi = 0; mi < 4; mi++)
                ldsm_x4(a[mi][0], a[mi][1], a[mi][2], a[mi][3], stg + aoff[mi] + kb);
            ldsm_x4(b[0][0], b[0][1], b[1][0], b[1][1], stg + boff + kb);
#pragma unroll
            for (int mi = 0; mi < 4; mi++)
#pragma unroll
                for (int ni = 0; ni < 2; ni++)
                    MMA_F16(acc[mi][ni], a[mi], b[ni]);
        }
    }
    __syncthreads();

    // Epilogue: stage transposed fp16 cbuf[k][r], coalesced write C1h (parity-major).
    __half* cbuf = (__half*)dsm;
#pragma unroll
    for (int mi = 0; mi < 4; mi++)
#pragma unroll
        for (int ni = 0; ni < 2; ni++) {
            int rl = wm * 64 + mi * 16 + g;
            int cl = wn * 16 + ni * 8 + t2;
            cbuf[cl * SLDE + rl]           = __float2half(acc[mi][ni][0]);
            cbuf[(cl + 1) * SLDE + rl]     = __float2half(acc[mi][ni][1]);
            cbuf[cl * SLDE + rl + 8]       = __float2half(acc[mi][ni][2]);
            cbuf[(cl + 1) * SLDE + rl + 8] = __float2half(acc[mi][ni][3]);
        }
    __syncthreads();
    int kgBase = p * MH + bn;
#pragma unroll
    for (int q = 0; q < 8; q++) {
        int idx = tid + q * 256;
        int kc = idx >> 5;
        int seg = (idx & 31) * 4;
        *(uint2*)&g_C1h[(kgBase + kc) * RROWS + bm + seg] = *(uint2*)&cbuf[kc * SLDE + seg];
    }
}

// ---------------------------------------------------------------------------
// Mix (tensor cores): per pk, C2h[pk][b*64+o] = sum_i C1h[pk][b*64+i]*Wt16[pk][i][o]
// ---------------------------------------------------------------------------
__global__ __launch_bounds__(128) void mix_mma_kernel() {
    int k = blockIdx.x;
    __shared__ __align__(16) __half sA[64][72];
    __shared__ __align__(16) __half sW[64][72];
    const __half* a = &g_C1h[k * RROWS];
    const __half* w = &g_Wt16[k * RROWS];
    int tid = (int)threadIdx.x;
#pragma unroll
    for (int l = 0; l < 4; l++) {
        int idx = tid + l * 128;
        int r = idx >> 3, seg = (idx & 7) * 8;
        *(uint4*)&sA[r][seg] = *(const uint4*)&a[r * 64 + seg];
        *(uint4*)&sW[r][seg] = *(const uint4*)&w[r * 64 + seg];
    }
    __syncthreads();

    int warp = tid >> 5, lane = tid & 31;
    int g = lane >> 2, t2 = (lane & 3) * 2;
    uint32_t sAb = (uint32_t)__cvta_generic_to_shared(&sA[0][0]);
    uint32_t sWb = (uint32_t)__cvta_generic_to_shared(&sW[0][0]);

    float acc[8][4];
#pragma unroll
    for (int i = 0; i < 8; i++)
#pragma unroll
        for (int j = 0; j < 4; j++) acc[i][j] = 0.0f;

#pragma unroll
    for (int ks = 0; ks < 4; ks++) {
        uint32_t av[4];
        uint32_t aaddr = sAb + ((warp * 16 + (lane & 15)) * 72 + ks * 16 + ((lane >> 4) << 3)) * 2;
        ldsm_x4(av[0], av[1], av[2], av[3], aaddr);
#pragma unroll
        for (int nq = 0; nq < 4; nq++) {
            uint32_t b0, b1, b2, b3;
            uint32_t baddr = sWb + ((ks * 16 + (lane & 15)) * 72 + nq * 16 + ((lane >> 4) << 3)) * 2;
            ldsm_x4_t(b0, b1, b2, b3, baddr);
            uint32_t bb0[2] = {b0, b1}, bb1[2] = {b2, b3};
            MMA_F16(acc[nq * 2], av, bb0);
            MMA_F16(acc[nq * 2 + 1], av, bb1);
        }
    }

    __half* c2 = &g_C2h[k * RROWS];
#pragma unroll
    for (int ni = 0; ni < 8; ni++) {
        int col = ni * 8 + t2;
        __half2 v0 = __floats2half2_rn(acc[ni][0], acc[ni][1]);
        __half2 v1 = __floats2half2_rn(acc[ni][2], acc[ni][3]);
        *(__half2*)&c2[(warp * 16 + g) * 64 + col]     = v0;
        *(__half2*)&c2[(warp * 16 + g + 8) * 64 + col] = v1;
    }
}

// ---------------------------------------------------------------------------
// GEMM3 (folded + butterfly), A consumed DIRECTLY from C2h[pk][r] via
// [k][r] smem staging + ldmatrix.trans fragments (no transpose kernel).
//   Se[r][n] = sum C2h[k2][r]*B3e[n][k2];  So likewise with odd.
//   out[r][n] = Se+So; out[r][2047-n] = Se-So   (n < 1024)
// ---------------------------------------------------------------------------
__global__ __launch_bounds__(256, 2) void gemm3_mma(float* __restrict__ out) {
    int tid = (int)threadIdx.x;
    int bm = blockIdx.y * 128;   // r
    int bn = blockIdx.x * 64;    // n (folded half)
    int warp = tid >> 5, lane = tid & 31;
    int wm = warp >> 2, wn = warp & 3;
    int g = lane >> 2, t2 = (lane & 3) * 2;

    uint32_t sbase = (uint32_t)__cvta_generic_to_shared(dsm);

    // A: 32 k-rows x 128 r halves per stage = 512 uint4 (2/thread)
    int aRow[2], aSeg[2];
#pragma unroll
    for (int l = 0; l < 2; l++) {
        int idx = tid + l * 256;
        aRow[l] = idx >> 4;           // 0..31
        aSeg[l] = (idx & 15) * 8;     // 0..120
    }
    // B: 64 n-rows x 32 k = 256 uint4 (1/thread)
    int bRow = tid >> 2, bSeg = (tid & 3) * 8;

    // A fragments via ldmatrix.trans from [k][r] tile
    uint32_t atoff[4];
#pragma unroll
    for (int mi = 0; mi < 4; mi++)
        atoff[mi] = (((((lane >> 4) & 1) * 8 + (lane & 7)) * SLDA) +
                     wm * 64 + mi * 16 + (((lane >> 3) & 1) * 8)) * 2;
    uint32_t boff = (uint32_t)(32 * SLDA * 2) +
                    ((wn * 16 + (lane & 7) + ((lane >> 4) << 3)) * SLD +
                     (((lane >> 3) & 1) << 3)) * 2;

    float acc_e[4][2][4], acc_o[4][2][4];
#pragma unroll
    for (int a = 0; a < 4; a++)
#pragma unroll
        for (int b = 0; b < 2; b++)
#pragma unroll
            for (int c = 0; c < 4; c++) { acc_e[a][b][c] = 0.0f; acc_o[a][b][c] = 0.0f; }

    // iteration j in [0,16): phase = j>>3, kk = (j&7)*32
#define G3_LOAD(j)                                                                   \
    do {                                                                             \
        int s_ = (j) & 3;                                                            \
        int ph_ = (j) >> 3;                                                          \
        int kk_ = ((j) & 7) * 32;                                                    \
        __half* sA_ = (__half*)(dsm + s_ * STG3_B);                                  \
        __half* sB_ = (__half*)(dsm + s_ * STG3_B + 32 * SLDA * 2);                  \
        const __half* Bs_ = ph_ ? g_B3o : g_B3e;                                     \
        _Pragma("unroll")                                                            \
        for (int l_ = 0; l_ < 2; l_++)                                               \
            cp_async16(&sA_[aRow[l_] * SLDA + aSeg[l_]],                             \
                       &g_C2h[(ph_ * MH + kk_ + aRow[l_]) * RROWS + bm + aSeg[l_]]); \
        cp_async16(&sB_[bRow * SLD + bSeg], &Bs_[(bn + bRow) * MH + kk_ + bSeg]);    \
        CP_COMMIT();                                                                 \
    } while (0)

#define G3_COMPUTE(j, ACC)                                                           \
    do {                                                                             \
        uint32_t stg_ = sbase + (uint32_t)(((j) & 3) * STG3_B);                      \
        _Pragma("unroll")                                                            \
        for (int ks_ = 0; ks_ < 2; ks_++) {                                          \
            uint32_t ka_ = (uint32_t)(ks_ * 16 * SLDA * 2);                          \
            uint32_t kb_ = (uint32_t)(ks_ * 32);                                     \
            uint32_t a_[4][4], b_[2][2];                                             \
            _Pragma("unroll")                                                        \
            for (int mi_ = 0; mi_ < 4; mi_++)                                        \
                ldsm_x4_t(a_[mi_][0], a_[mi_][1], a_[mi_][2], a_[mi_][3],            \
                          stg_ + atoff[mi_] + ka_);                                  \
            ldsm_x4(b_[0][0], b_[0][1], b_[1][0], b_[1][1], stg_ + boff + kb_);      \
            _Pragma("unroll")                                                        \
            for (int mi_ = 0; mi_ < 4; mi_++)                                        \
                _Pragma("unroll")                                                    \
                for (int ni_ = 0; ni_ < 2; ni_++)                                    \
                    MMA_F16(ACC[mi_][ni_], a_[mi_], b_[ni_]);                        \
        }                                                                            \
    } while (0)

#pragma unroll
    for (int s = 0; s < 3; s++) G3_LOAD(s);

    for (int j = 0; j < 8; j++) {
        CP_WAIT(2);
        __syncthreads();
        G3_LOAD(j + 3);
        G3_COMPUTE(j, acc_e);
        __syncthreads();
    }
    for (int j = 8; j < 16; j++) {
        CP_WAIT(2);
        __syncthreads();
        if (j + 3 < 16) G3_LOAD(j + 3);
        G3_COMPUTE(j, acc_o);
        __syncthreads();
    }

    // Butterfly epilogue: out[r][n] = e+o, out[r][2047-n] = e-o
#pragma unroll
    for (int mi = 0; mi < 4; mi++)
#pragma unroll
        for (int ni = 0; ni < 2; ni++) {
            int row = bm + wm * 64 + mi * 16 + g;
            int col = bn + wn * 16 + ni * 8 + t2;
            float e0 = acc_e[mi][ni][0], e1 = acc_e[mi][ni][1];
            float e2 = acc_e[mi][ni][2], e3 = acc_e[mi][ni][3];
            float o0 = acc_o[mi][ni][0], o1 = acc_o[mi][ni][1];
            float o2 = acc_o[mi][ni][2], o3 = acc_o[mi][ni][3];
            *(float2*)&out[row * NG + col]       = make_float2(e0 + o0, e1 + o1);
            *(float2*)&out[(row + 8) * NG + col] = make_float2(e2 + o2, e3 + o3);
            int mcol = NG - 2 - col;
            *(float2*)&out[row * NG + mcol]       = make_float2(e1 - o1, e0 - o0);
            *(float2*)&out[(row + 8) * NG + mcol] = make_float2(e3 - o3, e2 - o2);
        }
}

// ---------------------------------------------------------------------------
// Launch
// ---------------------------------------------------------------------------
extern "C" void kernel_launch(void* const* d_in, const int* in_sizes, int n_in,
                              void* d_out, int out_size) {
    const float* x = (const float*)d_in[0];   // [64, 64, 2048] f32
    const float* w = (const float*)d_in[1];   // [64, 64, 512]  f32
    float* out = (float*)d_out;               // [64, 64, 2048] f32

    cudaFuncSetAttribute(gemm1_mma, cudaFuncAttributeMaxDynamicSharedMemorySize, NSTG * STG_B);
    cudaFuncSetAttribute(gemm3_mma, cudaFuncAttributeMaxDynamicSharedMemorySize, NSTG * STG3_B);

    init_table_kernel<<<16, 256>>>();
    init_M_kernel<<<(MH * NH + 255) / 256, 256>>>();
    convert_X_kernel<<<(RROWS * (NH / 4) + 255) / 256, 256>>>(x);
    transpose_W_kernel<<<dim3(MODES / 64, RROWS / 32), 256>>>(w);
    gemm1_mma<<<dim3(MH / 64, RROWS / 128, 2), 256, NSTG * STG_B>>>();
    mix_mma_kernel<<<MODES, 128>>>();
    gemm3_mma<<<dim3(NH / 64, RROWS / 128), 256, NSTG * STG3_B>>>(out);
}